// round 2
// baseline (speedup 1.0000x reference)
#include <cuda_runtime.h>
#include <cuda_bf16.h>

#define RAYS 16384
#define NCS 64
#define NFS 128
#define NTS 192

__device__ float g_w[RAYS * NCS];   // coarse weights
__device__ float g_z[RAYS * NTS];   // merged z_vals

// ---------------------------------------------------------------------------
// MLP: x(3) -> relu(64) -> relu(64) -> [sigmoid rgb(3), relu density(1)]
// ---------------------------------------------------------------------------
__device__ __forceinline__ void mlp_eval(
    float px, float py, float pz,
    const float* __restrict__ sW1, const float* __restrict__ sB1,
    const float* __restrict__ sW2, const float* __restrict__ sB2,
    const float* __restrict__ sWr, const float* __restrict__ sBr,
    const float* __restrict__ sWd, float bd,
    float& rr, float& rg, float& rb, float& dens)
{
    float h2[64];
#pragma unroll
    for (int j = 0; j < 64; ++j) h2[j] = sB2[j];

#pragma unroll 4
    for (int k = 0; k < 64; ++k) {
        float v = sB1[k];
        v = fmaf(px, sW1[k], v);
        v = fmaf(py, sW1[64 + k], v);
        v = fmaf(pz, sW1[128 + k], v);
        float a = fmaxf(v, 0.0f);
        const float4* w4 = reinterpret_cast<const float4*>(sW2 + (k << 6));
#pragma unroll
        for (int q = 0; q < 16; ++q) {
            float4 w = w4[q];
            h2[4 * q + 0] = fmaf(a, w.x, h2[4 * q + 0]);
            h2[4 * q + 1] = fmaf(a, w.y, h2[4 * q + 1]);
            h2[4 * q + 2] = fmaf(a, w.z, h2[4 * q + 2]);
            h2[4 * q + 3] = fmaf(a, w.w, h2[4 * q + 3]);
        }
    }

    float a0 = sBr[0], a1 = sBr[1], a2 = sBr[2], ad = bd;
#pragma unroll
    for (int j = 0; j < 64; ++j) {
        float v = fmaxf(h2[j], 0.0f);
        a0 = fmaf(v, sWr[3 * j + 0], a0);
        a1 = fmaf(v, sWr[3 * j + 1], a1);
        a2 = fmaf(v, sWr[3 * j + 2], a2);
        ad = fmaf(v, sWd[j], ad);
    }
    rr = 1.0f / (1.0f + __expf(-a0));
    rg = 1.0f / (1.0f + __expf(-a1));
    rb = 1.0f / (1.0f + __expf(-a2));
    dens = fmaxf(ad, 0.0f);
}

// ---------------------------------------------------------------------------
// Kernel 1: coarse pass. 4 rays / block, 64 threads per ray (1 thread = 1 pt).
// ---------------------------------------------------------------------------
__global__ void __launch_bounds__(256) coarse_kernel(
    const float* __restrict__ origins, const float* __restrict__ dirs,
    const float* __restrict__ nearp, const float* __restrict__ farp,
    const float* __restrict__ bkgd,
    const float* __restrict__ W1, const float* __restrict__ B1,
    const float* __restrict__ W2, const float* __restrict__ B2,
    const float* __restrict__ Wr, const float* __restrict__ Br,
    const float* __restrict__ Wd, const float* __restrict__ Bd,
    float* __restrict__ out)
{
    __shared__ __align__(16) float sW1[192];
    __shared__ __align__(16) float sB1[64];
    __shared__ __align__(16) float sW2[4096];
    __shared__ __align__(16) float sB2[64];
    __shared__ __align__(16) float sWr[192];
    __shared__ __align__(16) float sWd[64];
    __shared__ float sBr[3];
    __shared__ float sBdv;
    __shared__ float sScan[4][2];
    __shared__ float sRed[4][2][6];

    const int tid = threadIdx.x;
    for (int x = tid; x < 192; x += 256) sW1[x] = W1[x];
    for (int x = tid; x < 64; x += 256) sB1[x] = B1[x];
    for (int x = tid; x < 4096; x += 256) sW2[x] = W2[x];
    for (int x = tid; x < 64; x += 256) sB2[x] = B2[x];
    for (int x = tid; x < 192; x += 256) sWr[x] = Wr[x];
    for (int x = tid; x < 64; x += 256) sWd[x] = Wd[x];
    if (tid < 3) sBr[tid] = Br[tid];
    if (tid == 0) sBdv = Bd[0];
    __syncthreads();

    const int r = tid >> 6;
    const int i = tid & 63;
    const int ray = blockIdx.x * 4 + r;

    const float nb = nearp[ray], fb = farp[ray];
    const float ti = (float)i * (1.0f / 63.0f);
    const float tin = (float)(i + 1) * (1.0f / 63.0f);
    const float t = nb * (1.0f - ti) + fb * ti;
    const float tnx = nb * (1.0f - tin) + fb * tin;

    const float ox = origins[3 * ray + 0], oy = origins[3 * ray + 1], oz = origins[3 * ray + 2];
    const float dx = dirs[3 * ray + 0], dy = dirs[3 * ray + 1], dz = dirs[3 * ray + 2];
    const float px = fmaf(t, dx, ox), py = fmaf(t, dy, oy), pz = fmaf(t, dz, oz);

    float rr, rg, rb2, dens;
    mlp_eval(px, py, pz, sW1, sB1, sW2, sB2, sWr, sBr, sWd, sBdv, rr, rg, rb2, dens);

    const float dn = sqrtf(dx * dx + dy * dy + dz * dz);
    const float tdist = (i == 63) ? 1e10f : (tnx - t);
    const float dd = dens * tdist * dn;

    // 64-wide EXCLUSIVE prefix sum of dd (2 warps per ray).
    // Exclusive value taken via shfl_up of the inclusive scan — NOT s-dd,
    // which catastrophically cancels at the last sample (dd ~ 1e10).
    const int lane = i & 31;
    const int wir = i >> 5;
    float s = dd;
#pragma unroll
    for (int off = 1; off < 32; off <<= 1) {
        float n = __shfl_up_sync(0xffffffffu, s, off);
        if (lane >= off) s += n;
    }
    if (lane == 31) sScan[r][wir] = s;
    __syncthreads();
    float prev = __shfl_up_sync(0xffffffffu, s, 1);
    float excl = (lane == 0) ? 0.0f : prev;
    if (wir) excl += sScan[r][0];

    const float alpha = 1.0f - __expf(-dd);
    const float w = alpha * __expf(-excl);
    g_w[ray * NCS + i] = w;

    // ray-0 t_vals (for the pts0 = sum(w * samples[0]) quirk)
    const float n0 = nearp[0], f0 = farp[0];
    const float t0 = n0 * (1.0f - ti) + f0 * ti;

    float v[6] = { w * rr, w * rg, w * rb2, w, w * t, w * t0 };
#pragma unroll
    for (int q = 0; q < 6; ++q) {
#pragma unroll
        for (int off = 16; off >= 1; off >>= 1)
            v[q] += __shfl_xor_sync(0xffffffffu, v[q], off);
    }
    if (lane == 0) {
#pragma unroll
        for (int q = 0; q < 6; ++q) sRed[r][wir][q] = v[q];
    }
    __syncthreads();
    if (i == 0) {
        const float c0 = sRed[r][0][0] + sRed[r][1][0];
        const float c1 = sRed[r][0][1] + sRed[r][1][1];
        const float c2 = sRed[r][0][2] + sRed[r][1][2];
        const float acc = sRed[r][0][3] + sRed[r][1][3];
        const float dep = sRed[r][0][4] + sRed[r][1][4];
        const float wt0 = sRed[r][0][5] + sRed[r][1][5];
        const float om = 1.0f - acc;
        float* o = out + (size_t)ray * 16;
        o[0] = c0 + bkgd[0] * om;
        o[1] = c1 + bkgd[1] * om;
        o[2] = c2 + bkgd[2] * om;
        o[3] = dep;
        o[4] = acc;
        o[5] = fmaf(wt0, dirs[0], acc * origins[0]);
        o[6] = fmaf(wt0, dirs[1], acc * origins[1]);
        o[7] = fmaf(wt0, dirs[2], acc * origins[2]);
    }
}

// ---------------------------------------------------------------------------
// Kernel 2: inverse-CDF sampling + merge-sort with t_vals. 1 thread per ray.
// ---------------------------------------------------------------------------
__global__ void __launch_bounds__(256) sample_kernel(
    const float* __restrict__ nearp, const float* __restrict__ farp)
{
    const int ray = blockIdx.x * blockDim.x + threadIdx.x;
    if (ray >= RAYS) return;
    const float nb = nearp[ray], fb = farp[ray];

    // weights w[1:-1] -> 62 bins over 63 midpoint edges
    float wl[62];
    float wsum = 0.0f;
    const float* gw = g_w + ray * NCS;
    for (int j = 0; j < 62; ++j) { wl[j] = gw[1 + j]; wsum += wl[j]; }
    const float pad = fmaxf(1e-5f - wsum, 0.0f);
    const float padd = pad * (1.0f / 62.0f);
    const float inv = 1.0f / (wsum + pad);

    float cdf[63];
    cdf[0] = 0.0f;
    float run = 0.0f;
    for (int j = 0; j < 61; ++j) {
        run += (wl[j] + padd) * inv;
        cdf[j + 1] = fminf(run, 1.0f);
    }
    cdf[62] = 1.0f;

#define TVAL(idx) (nb * (1.0f - (float)(idx) * (1.0f/63.0f)) + fb * ((float)(idx) * (1.0f/63.0f)))
#define BINV(idx) (0.5f * (TVAL(idx) + TVAL((idx)+1)))

    float zs[NFS];
    int k = 0;
    const float du = (1.0f - 1.1920929e-7f) * (1.0f / 127.0f);
    for (int sidx = 0; sidx < NFS; ++sidx) {
        const float u = (float)sidx * du;
        while (k < 61 && cdf[k + 1] <= u) ++k;
        const float c0 = cdf[k], c1 = cdf[k + 1];
        float tt = (u - c0) / (c1 - c0);
        tt = fminf(fmaxf(tt, 0.0f), 1.0f);
        const float b0 = BINV(k), b1 = BINV(k + 1);
        zs[sidx] = b0 + tt * (b1 - b0);
    }

    // merge sorted t_vals(64) and zs(128) -> z_vals(192)
    float* zout = g_z + (size_t)ray * NTS;
    int a = 0, b = 0;
    for (int m = 0; m < NTS; ++m) {
        const float ta = (a < NCS) ? TVAL(a) : 3.4e38f;
        const float tb = (b < NFS) ? zs[b] : 3.4e38f;
        if (ta <= tb) { zout[m] = ta; ++a; }
        else          { zout[m] = tb; ++b; }
    }
#undef TVAL
#undef BINV
}

// ---------------------------------------------------------------------------
// Kernel 3: fine pass. 1 ray / block, 192 threads (1 thread = 1 point).
// ---------------------------------------------------------------------------
__global__ void __launch_bounds__(192) fine_kernel(
    const float* __restrict__ origins, const float* __restrict__ dirs,
    const float* __restrict__ bkgd,
    const float* __restrict__ W1, const float* __restrict__ B1,
    const float* __restrict__ W2, const float* __restrict__ B2,
    const float* __restrict__ Wr, const float* __restrict__ Br,
    const float* __restrict__ Wd, const float* __restrict__ Bd,
    float* __restrict__ out)
{
    __shared__ __align__(16) float sW1[192];
    __shared__ __align__(16) float sB1[64];
    __shared__ __align__(16) float sW2[4096];
    __shared__ __align__(16) float sB2[64];
    __shared__ __align__(16) float sWr[192];
    __shared__ __align__(16) float sWd[64];
    __shared__ float sBr[3];
    __shared__ float sBdv;
    __shared__ float sZ[NTS];
    __shared__ float sScan[6];
    __shared__ float sRed[6][6];

    const int tid = threadIdx.x;
    const int ray = blockIdx.x;

    for (int x = tid; x < 192; x += 192) sW1[x] = W1[x];
    for (int x = tid; x < 64; x += 192) sB1[x] = B1[x];
    for (int x = tid; x < 4096; x += 192) sW2[x] = W2[x];
    for (int x = tid; x < 64; x += 192) sB2[x] = B2[x];
    for (int x = tid; x < 192; x += 192) sWr[x] = Wr[x];
    for (int x = tid; x < 64; x += 192) sWd[x] = Wd[x];
    if (tid < 3) sBr[tid] = Br[tid];
    if (tid == 0) sBdv = Bd[0];
    sZ[tid] = g_z[(size_t)ray * NTS + tid];
    const float z0 = g_z[tid];   // ray 0's z_vals (pts1 quirk)
    __syncthreads();

    const float z = sZ[tid];
    const float tdist = (tid == NTS - 1) ? 1e10f : (sZ[tid + 1] - z);

    const float ox = origins[3 * ray + 0], oy = origins[3 * ray + 1], oz = origins[3 * ray + 2];
    const float dx = dirs[3 * ray + 0], dy = dirs[3 * ray + 1], dz = dirs[3 * ray + 2];
    const float px = fmaf(z, dx, ox), py = fmaf(z, dy, oy), pz = fmaf(z, dz, oz);

    float rr, rg, rb2, dens;
    mlp_eval(px, py, pz, sW1, sB1, sW2, sB2, sWr, sBr, sWd, sBdv, rr, rg, rb2, dens);

    const float dn = sqrtf(dx * dx + dy * dy + dz * dz);
    const float dd = dens * tdist * dn;

    // 192-wide EXCLUSIVE prefix sum (6 warps) — shfl_up form, no s-dd cancellation.
    const int lane = tid & 31;
    const int wid = tid >> 5;
    float s = dd;
#pragma unroll
    for (int off = 1; off < 32; off <<= 1) {
        float n = __shfl_up_sync(0xffffffffu, s, off);
        if (lane >= off) s += n;
    }
    if (lane == 31) sScan[wid] = s;
    __syncthreads();
    float base = 0.0f;
#pragma unroll
    for (int q = 0; q < 6; ++q)
        if (q < wid) base += sScan[q];
    float prev = __shfl_up_sync(0xffffffffu, s, 1);
    const float excl = ((lane == 0) ? 0.0f : prev) + base;
    const float w = (1.0f - __expf(-dd)) * __expf(-excl);

    float v[6] = { w * rr, w * rg, w * rb2, w, w * z, w * z0 };
#pragma unroll
    for (int q = 0; q < 6; ++q) {
#pragma unroll
        for (int off = 16; off >= 1; off >>= 1)
            v[q] += __shfl_xor_sync(0xffffffffu, v[q], off);
    }
    if (lane == 0) {
#pragma unroll
        for (int q = 0; q < 6; ++q) sRed[wid][q] = v[q];
    }
    __syncthreads();
    if (tid == 0) {
        float acc6[6];
#pragma unroll
        for (int q = 0; q < 6; ++q) {
            float t = 0.0f;
#pragma unroll
            for (int ww = 0; ww < 6; ++ww) t += sRed[ww][q];
            acc6[q] = t;
        }
        const float acc = acc6[3];
        const float om = 1.0f - acc;
        float* o = out + (size_t)ray * 16;
        o[8]  = acc6[0] + bkgd[0] * om;
        o[9]  = acc6[1] + bkgd[1] * om;
        o[10] = acc6[2] + bkgd[2] * om;
        o[11] = acc6[4];
        o[12] = acc;
        o[13] = fmaf(acc6[5], dirs[0], acc * origins[0]);
        o[14] = fmaf(acc6[5], dirs[1], acc * origins[1]);
        o[15] = fmaf(acc6[5], dirs[2], acc * origins[2]);
    }
}

// ---------------------------------------------------------------------------
extern "C" void kernel_launch(void* const* d_in, const int* in_sizes, int n_in,
                              void* d_out, int out_size)
{
    (void)in_sizes; (void)n_in; (void)out_size;
    const float* origins = (const float*)d_in[0];
    const float* dirs    = (const float*)d_in[1];
    const float* nearp   = (const float*)d_in[2];
    const float* farp    = (const float*)d_in[3];
    const float* bkgd    = (const float*)d_in[4];
    const float* w1c = (const float*)d_in[5];
    const float* b1c = (const float*)d_in[6];
    const float* w2c = (const float*)d_in[7];
    const float* b2c = (const float*)d_in[8];
    const float* wrc = (const float*)d_in[9];
    const float* brc = (const float*)d_in[10];
    const float* wdc = (const float*)d_in[11];
    const float* bdc = (const float*)d_in[12];
    const float* w1f = (const float*)d_in[13];
    const float* b1f = (const float*)d_in[14];
    const float* w2f = (const float*)d_in[15];
    const float* b2f = (const float*)d_in[16];
    const float* wrf = (const float*)d_in[17];
    const float* brf = (const float*)d_in[18];
    const float* wdf = (const float*)d_in[19];
    const float* bdf = (const float*)d_in[20];
    float* out = (float*)d_out;

    coarse_kernel<<<RAYS / 4, 256>>>(origins, dirs, nearp, farp, bkgd,
                                     w1c, b1c, w2c, b2c, wrc, brc, wdc, bdc, out);
    sample_kernel<<<RAYS / 256, 256>>>(nearp, farp);
    fine_kernel<<<RAYS, 192>>>(origins, dirs, bkgd,
                               w1f, b1f, w2f, b2f, wrf, brf, wdf, bdf, out);
}

// round 3
// speedup vs baseline: 1.0506x; 1.0506x over previous
#include <cuda_runtime.h>
#include <cuda_bf16.h>

#define RAYS 16384
#define NCS 64
#define NFS 128
#define NTS 192

__device__ float g_w[RAYS * NCS];   // coarse weights
__device__ float g_z[RAYS * NTS];   // merged z_vals

// ---- packed f32x2 helpers (FFMA2 only reachable via explicit PTX) ----------
__device__ __forceinline__ unsigned long long ffma2(
    unsigned long long a, unsigned long long b, unsigned long long c)
{
    unsigned long long d;
    asm("fma.rn.f32x2 %0, %1, %2, %3;" : "=l"(d) : "l"(a), "l"(b), "l"(c));
    return d;
}
__device__ __forceinline__ unsigned long long pack2(float x, float y)
{
    unsigned long long d;
    asm("mov.b64 %0, {%1, %2};" : "=l"(d) : "f"(x), "f"(y));
    return d;
}
__device__ __forceinline__ void unpack2(unsigned long long p, float& x, float& y)
{
    asm("mov.b64 {%0, %1}, %2;" : "=f"(x), "=f"(y) : "l"(p));
}

// ---------------------------------------------------------------------------
// Dual-point MLP: two points share every weight load; layer2 in packed f32x2.
// h2 layout: 32 packed regs/point, pair p holds outputs {2p, 2p+1}.
// ---------------------------------------------------------------------------
__device__ __forceinline__ void mlp_eval2(
    float px0, float py0, float pz0,
    float px1, float py1, float pz1,
    const float* __restrict__ sW1, const float* __restrict__ sB1,
    const float* __restrict__ sW2, const float* __restrict__ sB2,
    const float* __restrict__ sWr, const float* __restrict__ sBr,
    const float* __restrict__ sWd, float bd,
    float& rr0, float& rg0, float& rb0, float& dens0,
    float& rr1, float& rg1, float& rb1, float& dens1)
{
    unsigned long long h2a[32], h2b[32];
    const unsigned long long* b2u = reinterpret_cast<const unsigned long long*>(sB2);
#pragma unroll
    for (int p = 0; p < 32; ++p) { unsigned long long b = b2u[p]; h2a[p] = b; h2b[p] = b; }

#pragma unroll 2
    for (int k = 0; k < 64; ++k) {
        const float wk0 = sW1[k], wk1 = sW1[64 + k], wk2 = sW1[128 + k], bk = sB1[k];
        float v0 = fmaf(px0, wk0, bk); v0 = fmaf(py0, wk1, v0); v0 = fmaf(pz0, wk2, v0);
        float v1 = fmaf(px1, wk0, bk); v1 = fmaf(py1, wk1, v1); v1 = fmaf(pz1, wk2, v1);
        const float a0 = fmaxf(v0, 0.0f), a1 = fmaxf(v1, 0.0f);
        const unsigned long long pa0 = pack2(a0, a0);
        const unsigned long long pa1 = pack2(a1, a1);
        const ulonglong2* w8 = reinterpret_cast<const ulonglong2*>(sW2 + (k << 6));
#pragma unroll
        for (int q = 0; q < 16; ++q) {
            ulonglong2 ww = w8[q];
            h2a[2 * q + 0] = ffma2(pa0, ww.x, h2a[2 * q + 0]);
            h2a[2 * q + 1] = ffma2(pa0, ww.y, h2a[2 * q + 1]);
            h2b[2 * q + 0] = ffma2(pa1, ww.x, h2b[2 * q + 0]);
            h2b[2 * q + 1] = ffma2(pa1, ww.y, h2b[2 * q + 1]);
        }
    }

    float a00 = sBr[0], a01 = sBr[1], a02 = sBr[2], ad0 = bd;
    float a10 = sBr[0], a11 = sBr[1], a12 = sBr[2], ad1 = bd;
#pragma unroll
    for (int p = 0; p < 32; ++p) {
        float x0, x1, y0, y1;
        unpack2(h2a[p], x0, x1);
        unpack2(h2b[p], y0, y1);
        const int j0 = 2 * p, j1 = 2 * p + 1;
        const float w00 = sWr[3 * j0 + 0], w01 = sWr[3 * j0 + 1], w02 = sWr[3 * j0 + 2], wd0 = sWd[j0];
        const float w10 = sWr[3 * j1 + 0], w11 = sWr[3 * j1 + 1], w12 = sWr[3 * j1 + 2], wd1 = sWd[j1];
        const float u0 = fmaxf(x0, 0.0f), u1 = fmaxf(x1, 0.0f);
        const float t0 = fmaxf(y0, 0.0f), t1 = fmaxf(y1, 0.0f);
        a00 = fmaf(u0, w00, a00); a01 = fmaf(u0, w01, a01); a02 = fmaf(u0, w02, a02); ad0 = fmaf(u0, wd0, ad0);
        a00 = fmaf(u1, w10, a00); a01 = fmaf(u1, w11, a01); a02 = fmaf(u1, w12, a02); ad0 = fmaf(u1, wd1, ad0);
        a10 = fmaf(t0, w00, a10); a11 = fmaf(t0, w01, a11); a12 = fmaf(t0, w02, a12); ad1 = fmaf(t0, wd0, ad1);
        a10 = fmaf(t1, w10, a10); a11 = fmaf(t1, w11, a11); a12 = fmaf(t1, w12, a12); ad1 = fmaf(t1, wd1, ad1);
    }
    rr0 = 1.0f / (1.0f + __expf(-a00));
    rg0 = 1.0f / (1.0f + __expf(-a01));
    rb0 = 1.0f / (1.0f + __expf(-a02));
    dens0 = fmaxf(ad0, 0.0f);
    rr1 = 1.0f / (1.0f + __expf(-a10));
    rg1 = 1.0f / (1.0f + __expf(-a11));
    rb1 = 1.0f / (1.0f + __expf(-a12));
    dens1 = fmaxf(ad1, 0.0f);
}

// ---------------------------------------------------------------------------
// Kernel 1: coarse. 4 rays/block, 1 warp per ray, 2 points per thread.
// ---------------------------------------------------------------------------
__global__ void __launch_bounds__(128) coarse_kernel(
    const float* __restrict__ origins, const float* __restrict__ dirs,
    const float* __restrict__ nearp, const float* __restrict__ farp,
    const float* __restrict__ bkgd,
    const float* __restrict__ W1, const float* __restrict__ B1,
    const float* __restrict__ W2, const float* __restrict__ B2,
    const float* __restrict__ Wr, const float* __restrict__ Br,
    const float* __restrict__ Wd, const float* __restrict__ Bd,
    float* __restrict__ out)
{
    __shared__ __align__(16) float sW1[192];
    __shared__ __align__(16) float sB1[64];
    __shared__ __align__(16) float sW2[4096];
    __shared__ __align__(16) float sB2[64];
    __shared__ __align__(16) float sWr[192];
    __shared__ __align__(16) float sWd[64];
    __shared__ float sBr[3];
    __shared__ float sBdv;

    const int tid = threadIdx.x;
    for (int x = tid; x < 192; x += 128) sW1[x] = W1[x];
    for (int x = tid; x < 64; x += 128) sB1[x] = B1[x];
    for (int x = tid; x < 4096; x += 128) sW2[x] = W2[x];
    for (int x = tid; x < 64; x += 128) sB2[x] = B2[x];
    for (int x = tid; x < 192; x += 128) sWr[x] = Wr[x];
    for (int x = tid; x < 64; x += 128) sWd[x] = Wd[x];
    if (tid < 3) sBr[tid] = Br[tid];
    if (tid == 0) sBdv = Bd[0];
    __syncthreads();

    const int r = tid >> 5;
    const int lane = tid & 31;
    const int ray = blockIdx.x * 4 + r;
    const int i0 = 2 * lane, i1 = 2 * lane + 1;

    const float nb = nearp[ray], fb = farp[ray];
    const float ti0 = (float)i0 * (1.0f / 63.0f);
    const float ti1 = (float)i1 * (1.0f / 63.0f);
    const float ti2 = (float)(i1 + 1) * (1.0f / 63.0f);
    const float t0 = nb * (1.0f - ti0) + fb * ti0;
    const float t1 = nb * (1.0f - ti1) + fb * ti1;
    const float t2 = nb * (1.0f - ti2) + fb * ti2;

    const float ox = origins[3 * ray + 0], oy = origins[3 * ray + 1], oz = origins[3 * ray + 2];
    const float dx = dirs[3 * ray + 0], dy = dirs[3 * ray + 1], dz = dirs[3 * ray + 2];

    float rr0, rg0, rb0, d0, rr1, rg1, rb1, d1;
    mlp_eval2(fmaf(t0, dx, ox), fmaf(t0, dy, oy), fmaf(t0, dz, oz),
              fmaf(t1, dx, ox), fmaf(t1, dy, oy), fmaf(t1, dz, oz),
              sW1, sB1, sW2, sB2, sWr, sBr, sWd, sBdv,
              rr0, rg0, rb0, d0, rr1, rg1, rb1, d1);

    const float dn = sqrtf(dx * dx + dy * dy + dz * dz);
    const float dd0 = d0 * (t1 - t0) * dn;
    const float dd1 = d1 * ((i1 == 63) ? 1e10f : (t2 - t1)) * dn;

    // warp-exclusive scan over per-thread sums (no cancellation w/ huge dd1)
    float s = dd0 + dd1;
#pragma unroll
    for (int off = 1; off < 32; off <<= 1) {
        float n = __shfl_up_sync(0xffffffffu, s, off);
        if (lane >= off) s += n;
    }
    float prev = __shfl_up_sync(0xffffffffu, s, 1);
    const float excl = (lane == 0) ? 0.0f : prev;

    const float w0 = (1.0f - __expf(-dd0)) * __expf(-excl);
    const float w1 = (1.0f - __expf(-dd1)) * __expf(-(excl + dd0));
    reinterpret_cast<unsigned long long*>(g_w)[ray * 32 + lane] = pack2(w0, w1);

    // ray-0 t_vals quirk for pts0
    const float n0 = nearp[0], f0 = farp[0];
    const float t00 = n0 * (1.0f - ti0) + f0 * ti0;
    const float t01 = n0 * (1.0f - ti1) + f0 * ti1;

    float v[6] = { fmaf(w0, rr0, w1 * rr1), fmaf(w0, rg0, w1 * rg1),
                   fmaf(w0, rb0, w1 * rb1), w0 + w1,
                   fmaf(w0, t0, w1 * t1),  fmaf(w0, t00, w1 * t01) };
#pragma unroll
    for (int q = 0; q < 6; ++q) {
#pragma unroll
        for (int off = 16; off >= 1; off >>= 1)
            v[q] += __shfl_xor_sync(0xffffffffu, v[q], off);
    }
    if (lane == 0) {
        const float acc = v[3];
        const float om = 1.0f - acc;
        float* o = out + (size_t)ray * 16;
        o[0] = v[0] + bkgd[0] * om;
        o[1] = v[1] + bkgd[1] * om;
        o[2] = v[2] + bkgd[2] * om;
        o[3] = v[4];
        o[4] = acc;
        o[5] = fmaf(v[5], dirs[0], acc * origins[0]);
        o[6] = fmaf(v[5], dirs[1], acc * origins[1]);
        o[7] = fmaf(v[5], dirs[2], acc * origins[2]);
    }
}

// ---------------------------------------------------------------------------
// Kernel 2: streaming inverse-CDF + merge; no local arrays (all registers).
// Identical FP op sequence to the array version (monotone k pointer).
// ---------------------------------------------------------------------------
__global__ void __launch_bounds__(256) sample_kernel(
    const float* __restrict__ nearp, const float* __restrict__ farp)
{
    const int ray = blockIdx.x * blockDim.x + threadIdx.x;
    if (ray >= RAYS) return;
    const float nb = nearp[ray], fb = farp[ray];
    const float* gw = g_w + ray * NCS;

    float wsum = 0.0f;
#pragma unroll
    for (int j = 0; j < 62; ++j) wsum += gw[1 + j];
    const float pad = fmaxf(1e-5f - wsum, 0.0f);
    const float padd = pad * (1.0f / 62.0f);
    const float inv = 1.0f / (wsum + pad);

#define TVAL(idx) (nb * (1.0f - (float)(idx) * (1.0f/63.0f)) + fb * ((float)(idx) * (1.0f/63.0f)))
#define BINV(idx) (0.5f * (TVAL(idx) + TVAL((idx)+1)))

    // streaming cdf state: c0 = cdf[k], c1 = cdf[k+1], run = raw cumsum p[0..k]
    int k = 0;
    float run = (gw[1] + padd) * inv;
    float c0 = 0.0f, c1 = fminf(run, 1.0f);

    const float du = (1.0f - 1.1920929e-7f) * (1.0f / 127.0f);
    float* zout = g_z + (size_t)ray * NTS;
    int a = 0, b = 0;
    float zb = 0.0f;
    bool zb_valid = false;
    for (int m = 0; m < NTS; ++m) {
        float tb;
        if (b < NFS) {
            if (!zb_valid) {
                const float u = (float)b * du;
                while (k < 61 && c1 <= u) {
                    c0 = c1; ++k;
                    if (k <= 60) { run += (gw[1 + k] + padd) * inv; c1 = fminf(run, 1.0f); }
                    else c1 = 1.0f;
                }
                float tt = (u - c0) / (c1 - c0);
                tt = fminf(fmaxf(tt, 0.0f), 1.0f);
                const float b0v = BINV(k), b1v = BINV(k + 1);
                zb = b0v + tt * (b1v - b0v);
                zb_valid = true;
            }
            tb = zb;
        } else tb = 3.4e38f;
        const float ta = (a < NCS) ? TVAL(a) : 3.4e38f;
        if (ta <= tb) { zout[m] = ta; ++a; }
        else          { zout[m] = tb; ++b; zb_valid = false; }
    }
#undef TVAL
#undef BINV
}

// ---------------------------------------------------------------------------
// Kernel 3: fine. 1 ray/block, 96 threads (3 warps), 2 points per thread.
// ---------------------------------------------------------------------------
__global__ void __launch_bounds__(96) fine_kernel(
    const float* __restrict__ origins, const float* __restrict__ dirs,
    const float* __restrict__ bkgd,
    const float* __restrict__ W1, const float* __restrict__ B1,
    const float* __restrict__ W2, const float* __restrict__ B2,
    const float* __restrict__ Wr, const float* __restrict__ Br,
    const float* __restrict__ Wd, const float* __restrict__ Bd,
    float* __restrict__ out)
{
    __shared__ __align__(16) float sW1[192];
    __shared__ __align__(16) float sB1[64];
    __shared__ __align__(16) float sW2[4096];
    __shared__ __align__(16) float sB2[64];
    __shared__ __align__(16) float sWr[192];
    __shared__ __align__(16) float sWd[64];
    __shared__ float sBr[3];
    __shared__ float sBdv;
    __shared__ float sZ[NTS];
    __shared__ float sScan[3];
    __shared__ float sRed[3][6];

    const int tid = threadIdx.x;
    const int ray = blockIdx.x;

    for (int x = tid; x < 192; x += 96) sW1[x] = W1[x];
    for (int x = tid; x < 64; x += 96) sB1[x] = B1[x];
    for (int x = tid; x < 4096; x += 96) sW2[x] = W2[x];
    for (int x = tid; x < 64; x += 96) sB2[x] = B2[x];
    for (int x = tid; x < 192; x += 96) sWr[x] = Wr[x];
    for (int x = tid; x < 64; x += 96) sWd[x] = Wd[x];
    if (tid < 3) sBr[tid] = Br[tid];
    if (tid == 0) sBdv = Bd[0];
    sZ[tid] = g_z[(size_t)ray * NTS + tid];
    sZ[96 + tid] = g_z[(size_t)ray * NTS + 96 + tid];
    const float z00 = g_z[2 * tid];        // ray-0 z_vals (pts1 quirk)
    const float z01 = g_z[2 * tid + 1];
    __syncthreads();

    const float zp0 = sZ[2 * tid];
    const float zp1 = sZ[2 * tid + 1];
    const float znx = (tid == 95) ? 0.0f : sZ[2 * tid + 2];
    const float tdist0 = zp1 - zp0;
    const float tdist1 = (tid == 95) ? 1e10f : (znx - zp1);

    const float ox = origins[3 * ray + 0], oy = origins[3 * ray + 1], oz = origins[3 * ray + 2];
    const float dx = dirs[3 * ray + 0], dy = dirs[3 * ray + 1], dz = dirs[3 * ray + 2];

    float rr0, rg0, rb0, d0, rr1, rg1, rb1, d1;
    mlp_eval2(fmaf(zp0, dx, ox), fmaf(zp0, dy, oy), fmaf(zp0, dz, oz),
              fmaf(zp1, dx, ox), fmaf(zp1, dy, oy), fmaf(zp1, dz, oz),
              sW1, sB1, sW2, sB2, sWr, sBr, sWd, sBdv,
              rr0, rg0, rb0, d0, rr1, rg1, rb1, d1);

    const float dn = sqrtf(dx * dx + dy * dy + dz * dz);
    const float dd0 = d0 * tdist0 * dn;
    const float dd1 = d1 * tdist1 * dn;

    const int lane = tid & 31;
    const int wr = tid >> 5;
    float s = dd0 + dd1;
#pragma unroll
    for (int off = 1; off < 32; off <<= 1) {
        float n = __shfl_up_sync(0xffffffffu, s, off);
        if (lane >= off) s += n;
    }
    if (lane == 31) sScan[wr] = s;
    __syncthreads();
    float base = 0.0f;
#pragma unroll
    for (int q = 0; q < 3; ++q)
        if (q < wr) base += sScan[q];
    float prev = __shfl_up_sync(0xffffffffu, s, 1);
    const float excl = ((lane == 0) ? 0.0f : prev) + base;

    const float w0 = (1.0f - __expf(-dd0)) * __expf(-excl);
    const float w1 = (1.0f - __expf(-dd1)) * __expf(-(excl + dd0));

    float v[6] = { fmaf(w0, rr0, w1 * rr1), fmaf(w0, rg0, w1 * rg1),
                   fmaf(w0, rb0, w1 * rb1), w0 + w1,
                   fmaf(w0, zp0, w1 * zp1), fmaf(w0, z00, w1 * z01) };
#pragma unroll
    for (int q = 0; q < 6; ++q) {
#pragma unroll
        for (int off = 16; off >= 1; off >>= 1)
            v[q] += __shfl_xor_sync(0xffffffffu, v[q], off);
    }
    if (lane == 0) {
#pragma unroll
        for (int q = 0; q < 6; ++q) sRed[wr][q] = v[q];
    }
    __syncthreads();
    if (tid == 0) {
        float acc6[6];
#pragma unroll
        for (int q = 0; q < 6; ++q)
            acc6[q] = sRed[0][q] + sRed[1][q] + sRed[2][q];
        const float acc = acc6[3];
        const float om = 1.0f - acc;
        float* o = out + (size_t)ray * 16;
        o[8]  = acc6[0] + bkgd[0] * om;
        o[9]  = acc6[1] + bkgd[1] * om;
        o[10] = acc6[2] + bkgd[2] * om;
        o[11] = acc6[4];
        o[12] = acc;
        o[13] = fmaf(acc6[5], dirs[0], acc * origins[0]);
        o[14] = fmaf(acc6[5], dirs[1], acc * origins[1]);
        o[15] = fmaf(acc6[5], dirs[2], acc * origins[2]);
    }
}

// ---------------------------------------------------------------------------
extern "C" void kernel_launch(void* const* d_in, const int* in_sizes, int n_in,
                              void* d_out, int out_size)
{
    (void)in_sizes; (void)n_in; (void)out_size;
    const float* origins = (const float*)d_in[0];
    const float* dirs    = (const float*)d_in[1];
    const float* nearp   = (const float*)d_in[2];
    const float* farp    = (const float*)d_in[3];
    const float* bkgd    = (const float*)d_in[4];
    const float* w1c = (const float*)d_in[5];
    const float* b1c = (const float*)d_in[6];
    const float* w2c = (const float*)d_in[7];
    const float* b2c = (const float*)d_in[8];
    const float* wrc = (const float*)d_in[9];
    const float* brc = (const float*)d_in[10];
    const float* wdc = (const float*)d_in[11];
    const float* bdc = (const float*)d_in[12];
    const float* w1f = (const float*)d_in[13];
    const float* b1f = (const float*)d_in[14];
    const float* w2f = (const float*)d_in[15];
    const float* b2f = (const float*)d_in[16];
    const float* wrf = (const float*)d_in[17];
    const float* brf = (const float*)d_in[18];
    const float* wdf = (const float*)d_in[19];
    const float* bdf = (const float*)d_in[20];
    float* out = (float*)d_out;

    coarse_kernel<<<RAYS / 4, 128>>>(origins, dirs, nearp, farp, bkgd,
                                     w1c, b1c, w2c, b2c, wrc, brc, wdc, bdc, out);
    sample_kernel<<<RAYS / 256, 256>>>(nearp, farp);
    fine_kernel<<<RAYS, 96>>>(origins, dirs, bkgd,
                              w1f, b1f, w2f, b2f, wrf, brf, wdf, bdf, out);
}

// round 6
// speedup vs baseline: 2.2502x; 2.1419x over previous
#include <cuda_runtime.h>
#include <cuda_bf16.h>
#include <cstdint>

#define RAYS 16384
#define NCS 64
#define NFS 128
#define NTS 192

#define WPB 10                       // warps per block
#define BLK (WPB * 32)
#define HROW 144                     // staging/weight row pitch (bytes)
#define HWARP (32 * HROW * 2)        // per-warp h staging: hi + lo = 9216 B
#define DYN_SMEM (WPB * HWARP)

__device__ float g_w[RAYS * NCS];                 // coarse weights
__device__ float g_z[RAYS * NTS];                 // merged z_vals
__device__ float4 g_rgbd[RAYS * (NCS + NTS)];     // per-point {r,g,b,density}

// ===========================================================================
// helpers
// ===========================================================================
__device__ __forceinline__ uint32_t smem_u32(const void* p) {
    uint32_t a;
    asm("{ .reg .u64 t; cvta.to.shared.u64 t, %1; cvt.u32.u64 %0, t; }" : "=r"(a) : "l"(p));
    return a;
}
__device__ __forceinline__ uint32_t lds32(uint32_t a) {
    uint32_t v;
    asm volatile("ld.shared.b32 %0, [%1];" : "=r"(v) : "r"(a));
    return v;
}
__device__ __forceinline__ void sts128(uint32_t a, uint32_t x, uint32_t y, uint32_t z, uint32_t w) {
    asm volatile("st.shared.v4.b32 [%0], {%1, %2, %3, %4};" :: "r"(a), "r"(x), "r"(y), "r"(z), "r"(w) : "memory");
}
__device__ __forceinline__ void ldm_x4(uint32_t* r, uint32_t addr) {
    asm volatile("ldmatrix.sync.aligned.m8n8.x4.shared.b16 {%0, %1, %2, %3}, [%4];"
                 : "=r"(r[0]), "=r"(r[1]), "=r"(r[2]), "=r"(r[3]) : "r"(addr));
}
__device__ __forceinline__ void mma16816(float* c, const uint32_t* a, uint32_t b0, uint32_t b1) {
    asm volatile(
        "mma.sync.aligned.m16n8k16.row.col.f32.bf16.bf16.f32 "
        "{%0, %1, %2, %3}, {%4, %5, %6, %7}, {%8, %9}, {%0, %1, %2, %3};"
        : "+f"(c[0]), "+f"(c[1]), "+f"(c[2]), "+f"(c[3])
        : "r"(a[0]), "r"(a[1]), "r"(a[2]), "r"(a[3]), "r"(b0), "r"(b1));
}
// pack two floats -> bf16x2 (lower = f0, upper = f1)
__device__ __forceinline__ uint32_t bf16x2_rn(float f0, float f1) {
    uint32_t r;
    asm("cvt.rn.bf16x2.f32 %0, %1, %2;" : "=r"(r) : "f"(f1), "f"(f0));
    return r;
}
// split pair into bf16 hi + bf16 residual lo
__device__ __forceinline__ void split2(float f0, float f1, uint32_t& hi, uint32_t& lo) {
    hi = bf16x2_rn(f0, f1);
    const float r0 = __uint_as_float(hi << 16);
    const float r1 = __uint_as_float(hi & 0xffff0000u);
    lo = bf16x2_rn(f0 - r0, f1 - r1);
}

// ===========================================================================
// Batched MLP via mma.sync bf16 (split-3, fp32 accum).
// 320 threads = 10 warps; warp = 32 points (M=32 -> two m16 tiles).
// mode 0: coarse (t from near/far); mode 1: fine (t from g_z).
// ===========================================================================
__global__ void __launch_bounds__(BLK, 1) mlp_kernel(
    int mode, int wtotal,
    const float* __restrict__ origins, const float* __restrict__ dirs,
    const float* __restrict__ nearp, const float* __restrict__ farp,
    const float* __restrict__ W1, const float* __restrict__ B1,
    const float* __restrict__ W2, const float* __restrict__ B2,
    const float* __restrict__ WR, const float* __restrict__ BR,
    const float* __restrict__ WD, const float* __restrict__ BD,
    float4* __restrict__ outp)
{
    __shared__ __align__(16) __nv_bfloat16 sW2H[64 * 72];  // W2^T [n][k], pitch 72
    __shared__ __align__(16) __nv_bfloat16 sW2L[64 * 72];
    __shared__ __align__(16) __nv_bfloat16 sW3H[8 * 72];   // [rgb,d,0..0][k]
    __shared__ __align__(16) __nv_bfloat16 sW3L[8 * 72];
    __shared__ __align__(16) float4 sW14[64];              // {w1x, w1y, w1z, b1}
    __shared__ float sB2[64];
    __shared__ float sBRD[4];
    __shared__ __align__(16) float sOut[WPB][32][12];

    extern __shared__ __align__(16) char dsm[];            // h1 staging hi/lo per warp

    const int tid = threadIdx.x;
    const int warp = tid >> 5;
    const int lane = tid & 31;

    // ---- stage weights ----
    for (int e = tid; e < 4096; e += BLK) {
        const int n = e >> 6, k = e & 63;
        const float w = W2[k * 64 + n];
        const __nv_bfloat16 hb = __float2bfloat16(w);
        sW2H[n * 72 + k] = hb;
        sW2L[n * 72 + k] = __float2bfloat16(w - __bfloat162float(hb));
    }
    for (int e = tid; e < 512; e += BLK) {
        const int n = e >> 6, k = e & 63;
        const float w = (n < 3) ? WR[k * 3 + n] : ((n == 3) ? WD[k] : 0.0f);
        const __nv_bfloat16 hb = __float2bfloat16(w);
        sW3H[n * 72 + k] = hb;
        sW3L[n * 72 + k] = __float2bfloat16(w - __bfloat162float(hb));
    }
    for (int e = tid; e < 64; e += BLK) {
        sW14[e] = make_float4(W1[e], W1[64 + e], W1[128 + e], B1[e]);
        sB2[e] = B2[e];
    }
    if (tid < 3) sBRD[tid] = BR[tid];
    if (tid == 3) sBRD[3] = BD[0];
    __syncthreads();

    const uint32_t hB = smem_u32(dsm) + warp * HWARP;      // hi; lo at +4608
    const uint32_t w2hB = smem_u32(sW2H);
    const uint32_t w2lB = smem_u32(sW2L);
    const uint32_t w3hB = smem_u32(sW3H);
    const uint32_t w3lB = smem_u32(sW3L);

    const uint32_t ldmOff = (lane & 15) * HROW + (lane >> 4) * 16;      // bytes
    const uint32_t bOff = (lane >> 2) * HROW + (lane & 3) * 4;          // bytes
    const int j0 = (lane & 3) * 2;
    const int g = lane >> 2;

    for (int wt = blockIdx.x * WPB + warp; wt < wtotal; wt += gridDim.x * WPB) {
        const int gp = wt * 32 + lane;

        // ---- point position ----
        int ray;
        float t;
        if (mode == 0) {
            ray = gp >> 6;
            const float u = (float)(gp & 63) * (1.0f / 63.0f);
            t = nearp[ray] * (1.0f - u) + farp[ray] * u;
        } else {
            ray = gp / NTS;
            t = g_z[gp];
        }
        const float px = fmaf(t, dirs[3 * ray + 0], origins[3 * ray + 0]);
        const float py = fmaf(t, dirs[3 * ray + 1], origins[3 * ray + 1]);
        const float pz = fmaf(t, dirs[3 * ray + 2], origins[3 * ray + 2]);

        // ---- layer 1 (scalar) -> split -> staging ----
#pragma unroll
        for (int c = 0; c < 4; ++c) {
            float f[16];
#pragma unroll
            for (int j = 0; j < 16; ++j) {
                const float4 w = sW14[c * 16 + j];
                f[j] = fmaxf(fmaf(px, w.x, fmaf(py, w.y, fmaf(pz, w.z, w.w))), 0.0f);
            }
            uint32_t hi[8], lo[8];
#pragma unroll
            for (int p = 0; p < 8; ++p) split2(f[2 * p], f[2 * p + 1], hi[p], lo[p]);
            const uint32_t a0 = hB + lane * HROW + c * 32;
            sts128(a0, hi[0], hi[1], hi[2], hi[3]);
            sts128(a0 + 16, hi[4], hi[5], hi[6], hi[7]);
            sts128(a0 + 4608, lo[0], lo[1], lo[2], lo[3]);
            sts128(a0 + 4608 + 16, lo[4], lo[5], lo[6], lo[7]);
        }
        __syncwarp();

        // ---- layer 2: C[2][8] += split-3 (Ahi*Bhi + Ahi*Blo + Alo*Bhi) ----
        float C[2][8][4];
#pragma unroll
        for (int mt = 0; mt < 2; ++mt)
#pragma unroll
            for (int nt = 0; nt < 8; ++nt)
#pragma unroll
                for (int q = 0; q < 4; ++q) C[mt][nt][q] = 0.0f;

#pragma unroll
        for (int kt = 0; kt < 4; ++kt) {
            uint32_t Ah[2][4], Al[2][4];
#pragma unroll
            for (int mt = 0; mt < 2; ++mt) {
                const uint32_t aa = hB + mt * (16 * HROW) + ldmOff + kt * 32;
                ldm_x4(Ah[mt], aa);
                ldm_x4(Al[mt], aa + 4608);
            }
            uint32_t bh[8][2], bl[8][2];
#pragma unroll
            for (int nt = 0; nt < 8; ++nt) {
                const uint32_t ba = nt * (8 * HROW) + bOff + kt * 32;
                bh[nt][0] = lds32(w2hB + ba);
                bh[nt][1] = lds32(w2hB + ba + 16);
                bl[nt][0] = lds32(w2lB + ba);
                bl[nt][1] = lds32(w2lB + ba + 16);
            }
#pragma unroll
            for (int mt = 0; mt < 2; ++mt)
#pragma unroll
                for (int nt = 0; nt < 8; ++nt) {
                    mma16816(C[mt][nt], Ah[mt], bh[nt][0], bh[nt][1]);
                    mma16816(C[mt][nt], Ah[mt], bl[nt][0], bl[nt][1]);
                    mma16816(C[mt][nt], Al[mt], bh[nt][0], bh[nt][1]);
                }
        }

        // ---- layer 3: A3 repacked straight from C regs (same lane layout) ----
        float C3[2][4];
#pragma unroll
        for (int mt = 0; mt < 2; ++mt)
#pragma unroll
            for (int q = 0; q < 4; ++q) C3[mt][q] = 0.0f;

#pragma unroll
        for (int kt = 0; kt < 4; ++kt) {
            const int nt0 = 2 * kt, nt1 = 2 * kt + 1;
            const float b00 = sB2[nt0 * 8 + j0], b01 = sB2[nt0 * 8 + j0 + 1];
            const float b10 = sB2[nt1 * 8 + j0], b11 = sB2[nt1 * 8 + j0 + 1];
            uint32_t A3h[2][4], A3l[2][4];
#pragma unroll
            for (int mt = 0; mt < 2; ++mt) {
                const float v00 = fmaxf(C[mt][nt0][0] + b00, 0.0f);
                const float v01 = fmaxf(C[mt][nt0][1] + b01, 0.0f);
                const float v02 = fmaxf(C[mt][nt0][2] + b00, 0.0f);
                const float v03 = fmaxf(C[mt][nt0][3] + b01, 0.0f);
                const float v10 = fmaxf(C[mt][nt1][0] + b10, 0.0f);
                const float v11 = fmaxf(C[mt][nt1][1] + b11, 0.0f);
                const float v12 = fmaxf(C[mt][nt1][2] + b10, 0.0f);
                const float v13 = fmaxf(C[mt][nt1][3] + b11, 0.0f);
                split2(v00, v01, A3h[mt][0], A3l[mt][0]);
                split2(v02, v03, A3h[mt][1], A3l[mt][1]);
                split2(v10, v11, A3h[mt][2], A3l[mt][2]);
                split2(v12, v13, A3h[mt][3], A3l[mt][3]);
            }
            const uint32_t ba = bOff + kt * 32;
            const uint32_t b3h0 = lds32(w3hB + ba), b3h1 = lds32(w3hB + ba + 16);
            const uint32_t b3l0 = lds32(w3lB + ba), b3l1 = lds32(w3lB + ba + 16);
#pragma unroll
            for (int mt = 0; mt < 2; ++mt) {
                mma16816(C3[mt], A3h[mt], b3h0, b3h1);
                mma16816(C3[mt], A3h[mt], b3l0, b3l1);
                mma16816(C3[mt], A3l[mt], b3h0, b3h1);
            }
        }

        // ---- stage outputs (cols 0..3 = r,g,b,dens), activate, store ----
        if ((lane & 3) < 2) {
#pragma unroll
            for (int mt = 0; mt < 2; ++mt) {
                const int rA = mt * 16 + g;
                *(float2*)&sOut[warp][rA][j0] = make_float2(C3[mt][0], C3[mt][1]);
                *(float2*)&sOut[warp][rA + 8][j0] = make_float2(C3[mt][2], C3[mt][3]);
            }
        }
        __syncwarp();
        const float4 o4 = *(const float4*)&sOut[warp][lane][0];
        const float lr = o4.x + sBRD[0];
        const float lg = o4.y + sBRD[1];
        const float lb = o4.z + sBRD[2];
        const float ld = o4.w + sBRD[3];
        outp[gp] = make_float4(1.0f / (1.0f + __expf(-lr)),
                               1.0f / (1.0f + __expf(-lg)),
                               1.0f / (1.0f + __expf(-lb)),
                               fmaxf(ld, 0.0f));
        __syncwarp();
    }
}

// ===========================================================================
// Coarse render: warp/ray, 2 samples/lane.
// ===========================================================================
__global__ void __launch_bounds__(256) coarse_render(
    const float* __restrict__ origins, const float* __restrict__ dirs,
    const float* __restrict__ nearp, const float* __restrict__ farp,
    const float* __restrict__ bkgd, float* __restrict__ out)
{
    const int lane = threadIdx.x & 31;
    const int ray = blockIdx.x * 8 + (threadIdx.x >> 5);
    const int i0 = 2 * lane, i1 = 2 * lane + 1;

    const float nb = nearp[ray], fb = farp[ray];
    const float ti0 = (float)i0 * (1.0f / 63.0f);
    const float ti1 = (float)i1 * (1.0f / 63.0f);
    const float ti2 = (float)(i1 + 1) * (1.0f / 63.0f);
    const float t0 = nb * (1.0f - ti0) + fb * ti0;
    const float t1 = nb * (1.0f - ti1) + fb * ti1;
    const float t2 = nb * (1.0f - ti2) + fb * ti2;

    const float dx = dirs[3 * ray + 0], dy = dirs[3 * ray + 1], dz = dirs[3 * ray + 2];
    const float dn = sqrtf(dx * dx + dy * dy + dz * dz);

    const float4 q0 = g_rgbd[ray * NCS + i0];
    const float4 q1 = g_rgbd[ray * NCS + i1];
    const float dd0 = q0.w * (t1 - t0) * dn;
    const float dd1 = q1.w * ((i1 == 63) ? 1e10f : (t2 - t1)) * dn;

    float s = dd0 + dd1;
#pragma unroll
    for (int off = 1; off < 32; off <<= 1) {
        float n = __shfl_up_sync(0xffffffffu, s, off);
        if (lane >= off) s += n;
    }
    const float prev = __shfl_up_sync(0xffffffffu, s, 1);
    const float excl = (lane == 0) ? 0.0f : prev;

    const float w0 = (1.0f - __expf(-dd0)) * __expf(-excl);
    const float w1 = (1.0f - __expf(-dd1)) * __expf(-(excl + dd0));
    {
        unsigned long long pk;
        asm("mov.b64 %0, {%1, %2};" : "=l"(pk) : "f"(w0), "f"(w1));
        reinterpret_cast<unsigned long long*>(g_w)[ray * 32 + lane] = pk;
    }

    const float n0 = nearp[0], f0 = farp[0];
    const float t00 = n0 * (1.0f - ti0) + f0 * ti0;
    const float t01 = n0 * (1.0f - ti1) + f0 * ti1;

    float v[6] = { fmaf(w0, q0.x, w1 * q1.x), fmaf(w0, q0.y, w1 * q1.y),
                   fmaf(w0, q0.z, w1 * q1.z), w0 + w1,
                   fmaf(w0, t0, w1 * t1), fmaf(w0, t00, w1 * t01) };
#pragma unroll
    for (int q = 0; q < 6; ++q) {
#pragma unroll
        for (int off = 16; off >= 1; off >>= 1)
            v[q] += __shfl_xor_sync(0xffffffffu, v[q], off);
    }
    if (lane == 0) {
        const float acc = v[3], om = 1.0f - acc;
        float* o = out + (size_t)ray * 16;
        o[0] = v[0] + bkgd[0] * om;
        o[1] = v[1] + bkgd[1] * om;
        o[2] = v[2] + bkgd[2] * om;
        o[3] = v[4];
        o[4] = acc;
        o[5] = fmaf(v[5], dirs[0], acc * origins[0]);
        o[6] = fmaf(v[5], dirs[1], acc * origins[1]);
        o[7] = fmaf(v[5], dirs[2], acc * origins[2]);
    }
}

// ===========================================================================
// Streaming inverse-CDF + merge (unchanged, passing since R3).
// ===========================================================================
__global__ void __launch_bounds__(256) sample_kernel(
    const float* __restrict__ nearp, const float* __restrict__ farp)
{
    const int ray = blockIdx.x * blockDim.x + threadIdx.x;
    if (ray >= RAYS) return;
    const float nb = nearp[ray], fb = farp[ray];
    const float* gw = g_w + ray * NCS;

    float wsum = 0.0f;
#pragma unroll
    for (int j = 0; j < 62; ++j) wsum += gw[1 + j];
    const float pad = fmaxf(1e-5f - wsum, 0.0f);
    const float padd = pad * (1.0f / 62.0f);
    const float inv = 1.0f / (wsum + pad);

#define TVAL(idx) (nb * (1.0f - (float)(idx) * (1.0f/63.0f)) + fb * ((float)(idx) * (1.0f/63.0f)))
#define BINV(idx) (0.5f * (TVAL(idx) + TVAL((idx)+1)))

    int k = 0;
    float run = (gw[1] + padd) * inv;
    float c0 = 0.0f, c1 = fminf(run, 1.0f);

    const float du = (1.0f - 1.1920929e-7f) * (1.0f / 127.0f);
    float* zout = g_z + (size_t)ray * NTS;
    int a = 0, b = 0;
    float zb = 0.0f;
    bool zb_valid = false;
    for (int m = 0; m < NTS; ++m) {
        float tb;
        if (b < NFS) {
            if (!zb_valid) {
                const float u = (float)b * du;
                while (k < 61 && c1 <= u) {
                    c0 = c1; ++k;
                    if (k <= 60) { run += (gw[1 + k] + padd) * inv; c1 = fminf(run, 1.0f); }
                    else c1 = 1.0f;
                }
                float tt = (u - c0) / (c1 - c0);
                tt = fminf(fmaxf(tt, 0.0f), 1.0f);
                const float b0v = BINV(k), b1v = BINV(k + 1);
                zb = b0v + tt * (b1v - b0v);
                zb_valid = true;
            }
            tb = zb;
        } else tb = 3.4e38f;
        const float ta = (a < NCS) ? TVAL(a) : 3.4e38f;
        if (ta <= tb) { zout[m] = ta; ++a; }
        else          { zout[m] = tb; ++b; zb_valid = false; }
    }
#undef TVAL
#undef BINV
}

// ===========================================================================
// Fine render: warp/ray, 6 samples/lane.
// ===========================================================================
__global__ void __launch_bounds__(256) fine_render(
    const float* __restrict__ origins, const float* __restrict__ dirs,
    const float* __restrict__ bkgd, float* __restrict__ out)
{
    const int lane = threadIdx.x & 31;
    const int ray = blockIdx.x * 8 + (threadIdx.x >> 5);
    const float4* sc = g_rgbd + RAYS * NCS + (size_t)ray * NTS;
    const float* zr = g_z + (size_t)ray * NTS;
    const int j0 = lane * 6;

    const float dx = dirs[3 * ray + 0], dy = dirs[3 * ray + 1], dz = dirs[3 * ray + 2];
    const float dn = sqrtf(dx * dx + dy * dy + dz * dz);

    float z[7];
#pragma unroll
    for (int s = 0; s < 6; ++s) z[s] = zr[j0 + s];
    z[6] = (lane == 31) ? 0.0f : zr[j0 + 6];

    float dd[6], pre[6];
    float running = 0.0f;
#pragma unroll
    for (int s = 0; s < 6; ++s) {
        const float td = (lane == 31 && s == 5) ? 1e10f : (z[s + 1] - z[s]);
        dd[s] = sc[j0 + s].w * td * dn;
        running += dd[s];
        pre[s] = running;
    }

    float ssum = pre[5];
#pragma unroll
    for (int off = 1; off < 32; off <<= 1) {
        float n = __shfl_up_sync(0xffffffffu, ssum, off);
        if (lane >= off) ssum += n;
    }
    const float prev = __shfl_up_sync(0xffffffffu, ssum, 1);
    const float base = (lane == 0) ? 0.0f : prev;

    float v[6] = {0.0f, 0.0f, 0.0f, 0.0f, 0.0f, 0.0f};
#pragma unroll
    for (int s = 0; s < 6; ++s) {
        const float excl = base + ((s == 0) ? 0.0f : pre[s - 1]);
        const float w = (1.0f - __expf(-dd[s])) * __expf(-excl);
        const float4 q = sc[j0 + s];
        v[0] = fmaf(w, q.x, v[0]);
        v[1] = fmaf(w, q.y, v[1]);
        v[2] = fmaf(w, q.z, v[2]);
        v[3] += w;
        v[4] = fmaf(w, z[s], v[4]);
        v[5] = fmaf(w, g_z[j0 + s], v[5]);   // ray-0 z (pts1 quirk)
    }
#pragma unroll
    for (int q = 0; q < 6; ++q) {
#pragma unroll
        for (int off = 16; off >= 1; off >>= 1)
            v[q] += __shfl_xor_sync(0xffffffffu, v[q], off);
    }
    if (lane == 0) {
        const float acc = v[3], om = 1.0f - acc;
        float* o = out + (size_t)ray * 16;
        o[8]  = v[0] + bkgd[0] * om;
        o[9]  = v[1] + bkgd[1] * om;
        o[10] = v[2] + bkgd[2] * om;
        o[11] = v[4];
        o[12] = acc;
        o[13] = fmaf(v[5], dirs[0], acc * origins[0]);
        o[14] = fmaf(v[5], dirs[1], acc * origins[1]);
        o[15] = fmaf(v[5], dirs[2], acc * origins[2]);
    }
}

// ===========================================================================
extern "C" void kernel_launch(void* const* d_in, const int* in_sizes, int n_in,
                              void* d_out, int out_size)
{
    (void)in_sizes; (void)n_in; (void)out_size;
    const float* origins = (const float*)d_in[0];
    const float* dirs    = (const float*)d_in[1];
    const float* nearp   = (const float*)d_in[2];
    const float* farp    = (const float*)d_in[3];
    const float* bkgd    = (const float*)d_in[4];
    const float* w1c = (const float*)d_in[5];
    const float* b1c = (const float*)d_in[6];
    const float* w2c = (const float*)d_in[7];
    const float* b2c = (const float*)d_in[8];
    const float* wrc = (const float*)d_in[9];
    const float* brc = (const float*)d_in[10];
    const float* wdc = (const float*)d_in[11];
    const float* bdc = (const float*)d_in[12];
    const float* w1f = (const float*)d_in[13];
    const float* b1f = (const float*)d_in[14];
    const float* w2f = (const float*)d_in[15];
    const float* b2f = (const float*)d_in[16];
    const float* wrf = (const float*)d_in[17];
    const float* brf = (const float*)d_in[18];
    const float* wdf = (const float*)d_in[19];
    const float* bdf = (const float*)d_in[20];
    float* out = (float*)d_out;

    cudaFuncSetAttribute(mlp_kernel, cudaFuncAttributeMaxDynamicSharedMemorySize, DYN_SMEM);

    float4* scratch;
    cudaGetSymbolAddress((void**)&scratch, g_rgbd);

    const int wt_coarse = RAYS * NCS / 32;    // 32768 warp-tiles
    const int wt_fine   = RAYS * NTS / 32;    // 98304 warp-tiles

    mlp_kernel<<<148, BLK, DYN_SMEM>>>(0, wt_coarse, origins, dirs, nearp, farp,
                                       w1c, b1c, w2c, b2c, wrc, brc, wdc, bdc, scratch);
    coarse_render<<<RAYS / 8, 256>>>(origins, dirs, nearp, farp, bkgd, out);
    sample_kernel<<<RAYS / 256, 256>>>(nearp, farp);
    mlp_kernel<<<148, BLK, DYN_SMEM>>>(1, wt_fine, origins, dirs, nearp, farp,
                                       w1f, b1f, w2f, b2f, wrf, brf, wdf, bdf,
                                       scratch + RAYS * NCS);
    fine_render<<<RAYS / 8, 256>>>(origins, dirs, bkgd, out);
}

// round 7
// speedup vs baseline: 2.3695x; 1.0530x over previous
#include <cuda_runtime.h>
#include <cuda_bf16.h>
#include <cstdint>

#define RAYS 16384
#define NCS 64
#define NFS 128
#define NTS 192

#define WPB 14                       // warps per block
#define BLK (WPB * 32)
#define HROW 144                     // staging/weight row pitch (bytes)
#define HWARP (32 * HROW * 2)        // per-warp h staging: hi + lo = 9216 B
#define DYN_SMEM (WPB * HWARP)

__device__ float g_w[RAYS * NCS];                 // coarse weights
__device__ float g_z[RAYS * NTS];                 // merged z_vals
__device__ float4 g_rgbd[RAYS * (NCS + NTS)];     // per-point {r,g,b,density}

// ===========================================================================
// helpers
// ===========================================================================
__device__ __forceinline__ uint32_t smem_u32(const void* p) {
    uint32_t a;
    asm("{ .reg .u64 t; cvta.to.shared.u64 t, %1; cvt.u32.u64 %0, t; }" : "=r"(a) : "l"(p));
    return a;
}
__device__ __forceinline__ void lds64(uint32_t a, uint32_t& x, uint32_t& y) {
    asm volatile("ld.shared.v2.b32 {%0, %1}, [%2];" : "=r"(x), "=r"(y) : "r"(a));
}
__device__ __forceinline__ void sts128(uint32_t a, uint32_t x, uint32_t y, uint32_t z, uint32_t w) {
    asm volatile("st.shared.v4.b32 [%0], {%1, %2, %3, %4};" :: "r"(a), "r"(x), "r"(y), "r"(z), "r"(w) : "memory");
}
__device__ __forceinline__ void ldm_x4(uint32_t* r, uint32_t addr) {
    asm volatile("ldmatrix.sync.aligned.m8n8.x4.shared.b16 {%0, %1, %2, %3}, [%4];"
                 : "=r"(r[0]), "=r"(r[1]), "=r"(r[2]), "=r"(r[3]) : "r"(addr));
}
__device__ __forceinline__ void mma16816(float* c, const uint32_t* a, uint32_t b0, uint32_t b1) {
    asm volatile(
        "mma.sync.aligned.m16n8k16.row.col.f32.bf16.bf16.f32 "
        "{%0, %1, %2, %3}, {%4, %5, %6, %7}, {%8, %9}, {%0, %1, %2, %3};"
        : "+f"(c[0]), "+f"(c[1]), "+f"(c[2]), "+f"(c[3])
        : "r"(a[0]), "r"(a[1]), "r"(a[2]), "r"(a[3]), "r"(b0), "r"(b1));
}
// pack two floats -> bf16x2 (lower = f0, upper = f1)
__device__ __forceinline__ uint32_t bf16x2_rn(float f0, float f1) {
    uint32_t r;
    asm("cvt.rn.bf16x2.f32 %0, %1, %2;" : "=r"(r) : "f"(f1), "f"(f0));
    return r;
}
// split pair into bf16 hi + bf16 residual lo
__device__ __forceinline__ void split2(float f0, float f1, uint32_t& hi, uint32_t& lo) {
    hi = bf16x2_rn(f0, f1);
    const float r0 = __uint_as_float(hi << 16);
    const float r1 = __uint_as_float(hi & 0xffff0000u);
    lo = bf16x2_rn(f0 - r0, f1 - r1);
}
// permuted B-weight byte offset within a row: lane's two fragment regs adjacent.
// k = kt*16 + 8*half + 2*q + lo  ->  off = kt*32 + q*8 + half*4 + lo*2
__device__ __forceinline__ uint32_t bperm_off(int k) {
    const int kt = k >> 4, r = k & 15;
    return (uint32_t)(kt * 32 + ((r & 7) >> 1) * 8 + (r >> 3) * 4 + (r & 1) * 2);
}

// ===========================================================================
// Batched MLP via mma.sync bf16 (split-3, fp32 accum).
// 448 threads = 14 warps; warp = 32 points (M=32 -> two m16 tiles).
// mode 0: coarse (t from near/far); mode 1: fine (t from g_z).
// ===========================================================================
__global__ void __launch_bounds__(BLK, 1) mlp_kernel(
    int mode, int wtotal,
    const float* __restrict__ origins, const float* __restrict__ dirs,
    const float* __restrict__ nearp, const float* __restrict__ farp,
    const float* __restrict__ W1, const float* __restrict__ B1,
    const float* __restrict__ W2, const float* __restrict__ B2,
    const float* __restrict__ WR, const float* __restrict__ BR,
    const float* __restrict__ WD, const float* __restrict__ BD,
    float4* __restrict__ outp)
{
    __shared__ __align__(16) __nv_bfloat16 sW2H[64 * 72];  // W2^T [n][perm k], pitch 72
    __shared__ __align__(16) __nv_bfloat16 sW2L[64 * 72];
    __shared__ __align__(16) __nv_bfloat16 sW3H[8 * 72];   // [rgb,d,0..0][perm k]
    __shared__ __align__(16) __nv_bfloat16 sW3L[8 * 72];
    __shared__ __align__(16) float4 sW14[64];              // {w1x, w1y, w1z, b1}
    __shared__ float sB2[64];
    __shared__ float sBRD[4];
    __shared__ __align__(16) float sOut[WPB][32][12];

    extern __shared__ __align__(16) char dsm[];            // h1 staging hi/lo per warp

    const int tid = threadIdx.x;
    const int warp = tid >> 5;
    const int lane = tid & 31;

    // ---- stage weights (permuted k layout for v2 fragment loads) ----
    for (int e = tid; e < 4096; e += BLK) {
        const int n = e >> 6, k = e & 63;
        const float w = W2[k * 64 + n];
        const __nv_bfloat16 hb = __float2bfloat16(w);
        const uint32_t off = (uint32_t)n * HROW + bperm_off(k);
        *(__nv_bfloat16*)((char*)sW2H + off) = hb;
        *(__nv_bfloat16*)((char*)sW2L + off) = __float2bfloat16(w - __bfloat162float(hb));
    }
    for (int e = tid; e < 512; e += BLK) {
        const int n = e >> 6, k = e & 63;
        const float w = (n < 3) ? WR[k * 3 + n] : ((n == 3) ? WD[k] : 0.0f);
        const __nv_bfloat16 hb = __float2bfloat16(w);
        const uint32_t off = (uint32_t)n * HROW + bperm_off(k);
        *(__nv_bfloat16*)((char*)sW3H + off) = hb;
        *(__nv_bfloat16*)((char*)sW3L + off) = __float2bfloat16(w - __bfloat162float(hb));
    }
    for (int e = tid; e < 64; e += BLK) {
        sW14[e] = make_float4(W1[e], W1[64 + e], W1[128 + e], B1[e]);
        sB2[e] = B2[e];
    }
    if (tid < 3) sBRD[tid] = BR[tid];
    if (tid == 3) sBRD[3] = BD[0];
    __syncthreads();

    const uint32_t hB = smem_u32(dsm) + warp * HWARP;      // hi; lo at +4608
    const uint32_t w2hB = smem_u32(sW2H);
    const uint32_t w2lB = smem_u32(sW2L);
    const uint32_t w3hB = smem_u32(sW3H);
    const uint32_t w3lB = smem_u32(sW3L);

    const uint32_t ldmOff = (lane & 15) * HROW + (lane >> 4) * 16;      // bytes
    const uint32_t bOff = (lane >> 2) * HROW + (lane & 3) * 8;          // bytes (v2 layout)
    const int j0 = (lane & 3) * 2;
    const int g = lane >> 2;

    for (int wt = blockIdx.x * WPB + warp; wt < wtotal; wt += gridDim.x * WPB) {
        const int gp = wt * 32 + lane;

        // ---- point position ----
        int ray;
        float t;
        if (mode == 0) {
            ray = gp >> 6;
            const float u = (float)(gp & 63) * (1.0f / 63.0f);
            t = nearp[ray] * (1.0f - u) + farp[ray] * u;
        } else {
            ray = gp / NTS;
            t = g_z[gp];
        }
        const float px = fmaf(t, dirs[3 * ray + 0], origins[3 * ray + 0]);
        const float py = fmaf(t, dirs[3 * ray + 1], origins[3 * ray + 1]);
        const float pz = fmaf(t, dirs[3 * ray + 2], origins[3 * ray + 2]);

        // ---- layer 1 (scalar) -> split -> staging ----
#pragma unroll
        for (int c = 0; c < 4; ++c) {
            float f[16];
#pragma unroll
            for (int j = 0; j < 16; ++j) {
                const float4 w = sW14[c * 16 + j];
                f[j] = fmaxf(fmaf(px, w.x, fmaf(py, w.y, fmaf(pz, w.z, w.w))), 0.0f);
            }
            uint32_t hi[8], lo[8];
#pragma unroll
            for (int p = 0; p < 8; ++p) split2(f[2 * p], f[2 * p + 1], hi[p], lo[p]);
            const uint32_t a0 = hB + lane * HROW + c * 32;
            sts128(a0, hi[0], hi[1], hi[2], hi[3]);
            sts128(a0 + 16, hi[4], hi[5], hi[6], hi[7]);
            sts128(a0 + 4608, lo[0], lo[1], lo[2], lo[3]);
            sts128(a0 + 4608 + 16, lo[4], lo[5], lo[6], lo[7]);
        }
        __syncwarp();

        // ---- layer 2: C[2][8] += split-3 (Ahi*Bhi + Ahi*Blo + Alo*Bhi) ----
        float C[2][8][4];
#pragma unroll
        for (int mt = 0; mt < 2; ++mt)
#pragma unroll
            for (int nt = 0; nt < 8; ++nt)
#pragma unroll
                for (int q = 0; q < 4; ++q) C[mt][nt][q] = 0.0f;

#pragma unroll
        for (int kt = 0; kt < 4; ++kt) {
            uint32_t Ah[2][4], Al[2][4];
#pragma unroll
            for (int mt = 0; mt < 2; ++mt) {
                const uint32_t aa = hB + mt * (16 * HROW) + ldmOff + kt * 32;
                ldm_x4(Ah[mt], aa);
                ldm_x4(Al[mt], aa + 4608);
            }
            uint32_t bh[8][2], bl[8][2];
#pragma unroll
            for (int nt = 0; nt < 8; ++nt) {
                const uint32_t ba = nt * (8 * HROW) + bOff + kt * 32;
                lds64(w2hB + ba, bh[nt][0], bh[nt][1]);
                lds64(w2lB + ba, bl[nt][0], bl[nt][1]);
            }
#pragma unroll
            for (int mt = 0; mt < 2; ++mt)
#pragma unroll
                for (int nt = 0; nt < 8; ++nt) {
                    mma16816(C[mt][nt], Ah[mt], bh[nt][0], bh[nt][1]);
                    mma16816(C[mt][nt], Ah[mt], bl[nt][0], bl[nt][1]);
                    mma16816(C[mt][nt], Al[mt], bh[nt][0], bh[nt][1]);
                }
        }

        // ---- layer 3: A3 repacked straight from C regs (same lane layout) ----
        float C3[2][4];
#pragma unroll
        for (int mt = 0; mt < 2; ++mt)
#pragma unroll
            for (int q = 0; q < 4; ++q) C3[mt][q] = 0.0f;

#pragma unroll
        for (int kt = 0; kt < 4; ++kt) {
            const int nt0 = 2 * kt, nt1 = 2 * kt + 1;
            const float b00 = sB2[nt0 * 8 + j0], b01 = sB2[nt0 * 8 + j0 + 1];
            const float b10 = sB2[nt1 * 8 + j0], b11 = sB2[nt1 * 8 + j0 + 1];
            uint32_t A3h[2][4], A3l[2][4];
#pragma unroll
            for (int mt = 0; mt < 2; ++mt) {
                const float v00 = fmaxf(C[mt][nt0][0] + b00, 0.0f);
                const float v01 = fmaxf(C[mt][nt0][1] + b01, 0.0f);
                const float v02 = fmaxf(C[mt][nt0][2] + b00, 0.0f);
                const float v03 = fmaxf(C[mt][nt0][3] + b01, 0.0f);
                const float v10 = fmaxf(C[mt][nt1][0] + b10, 0.0f);
                const float v11 = fmaxf(C[mt][nt1][1] + b11, 0.0f);
                const float v12 = fmaxf(C[mt][nt1][2] + b10, 0.0f);
                const float v13 = fmaxf(C[mt][nt1][3] + b11, 0.0f);
                split2(v00, v01, A3h[mt][0], A3l[mt][0]);
                split2(v02, v03, A3h[mt][1], A3l[mt][1]);
                split2(v10, v11, A3h[mt][2], A3l[mt][2]);
                split2(v12, v13, A3h[mt][3], A3l[mt][3]);
            }
            uint32_t b3h0, b3h1, b3l0, b3l1;
            lds64(w3hB + bOff + kt * 32, b3h0, b3h1);
            lds64(w3lB + bOff + kt * 32, b3l0, b3l1);
#pragma unroll
            for (int mt = 0; mt < 2; ++mt) {
                mma16816(C3[mt], A3h[mt], b3h0, b3h1);
                mma16816(C3[mt], A3h[mt], b3l0, b3l1);
                mma16816(C3[mt], A3l[mt], b3h0, b3h1);
            }
        }

        // ---- stage outputs (cols 0..3 = r,g,b,dens), activate, store ----
        if ((lane & 3) < 2) {
#pragma unroll
            for (int mt = 0; mt < 2; ++mt) {
                const int rA = mt * 16 + g;
                *(float2*)&sOut[warp][rA][j0] = make_float2(C3[mt][0], C3[mt][1]);
                *(float2*)&sOut[warp][rA + 8][j0] = make_float2(C3[mt][2], C3[mt][3]);
            }
        }
        __syncwarp();
        const float4 o4 = *(const float4*)&sOut[warp][lane][0];
        const float lr = o4.x + sBRD[0];
        const float lg = o4.y + sBRD[1];
        const float lb = o4.z + sBRD[2];
        const float ld = o4.w + sBRD[3];
        outp[gp] = make_float4(1.0f / (1.0f + __expf(-lr)),
                               1.0f / (1.0f + __expf(-lg)),
                               1.0f / (1.0f + __expf(-lb)),
                               fmaxf(ld, 0.0f));
        __syncwarp();
    }
}

// ===========================================================================
// Coarse render: warp/ray, 2 samples/lane.
// ===========================================================================
__global__ void __launch_bounds__(256) coarse_render(
    const float* __restrict__ origins, const float* __restrict__ dirs,
    const float* __restrict__ nearp, const float* __restrict__ farp,
    const float* __restrict__ bkgd, float* __restrict__ out)
{
    const int lane = threadIdx.x & 31;
    const int ray = blockIdx.x * 8 + (threadIdx.x >> 5);
    const int i0 = 2 * lane, i1 = 2 * lane + 1;

    const float nb = nearp[ray], fb = farp[ray];
    const float ti0 = (float)i0 * (1.0f / 63.0f);
    const float ti1 = (float)i1 * (1.0f / 63.0f);
    const float ti2 = (float)(i1 + 1) * (1.0f / 63.0f);
    const float t0 = nb * (1.0f - ti0) + fb * ti0;
    const float t1 = nb * (1.0f - ti1) + fb * ti1;
    const float t2 = nb * (1.0f - ti2) + fb * ti2;

    const float dx = dirs[3 * ray + 0], dy = dirs[3 * ray + 1], dz = dirs[3 * ray + 2];
    const float dn = sqrtf(dx * dx + dy * dy + dz * dz);

    const float4 q0 = g_rgbd[ray * NCS + i0];
    const float4 q1 = g_rgbd[ray * NCS + i1];
    const float dd0 = q0.w * (t1 - t0) * dn;
    const float dd1 = q1.w * ((i1 == 63) ? 1e10f : (t2 - t1)) * dn;

    float s = dd0 + dd1;
#pragma unroll
    for (int off = 1; off < 32; off <<= 1) {
        float n = __shfl_up_sync(0xffffffffu, s, off);
        if (lane >= off) s += n;
    }
    const float prev = __shfl_up_sync(0xffffffffu, s, 1);
    const float excl = (lane == 0) ? 0.0f : prev;

    const float w0 = (1.0f - __expf(-dd0)) * __expf(-excl);
    const float w1 = (1.0f - __expf(-dd1)) * __expf(-(excl + dd0));
    {
        unsigned long long pk;
        asm("mov.b64 %0, {%1, %2};" : "=l"(pk) : "f"(w0), "f"(w1));
        reinterpret_cast<unsigned long long*>(g_w)[ray * 32 + lane] = pk;
    }

    const float n0 = nearp[0], f0 = farp[0];
    const float t00 = n0 * (1.0f - ti0) + f0 * ti0;
    const float t01 = n0 * (1.0f - ti1) + f0 * ti1;

    float v[6] = { fmaf(w0, q0.x, w1 * q1.x), fmaf(w0, q0.y, w1 * q1.y),
                   fmaf(w0, q0.z, w1 * q1.z), w0 + w1,
                   fmaf(w0, t0, w1 * t1), fmaf(w0, t00, w1 * t01) };
#pragma unroll
    for (int q = 0; q < 6; ++q) {
#pragma unroll
        for (int off = 16; off >= 1; off >>= 1)
            v[q] += __shfl_xor_sync(0xffffffffu, v[q], off);
    }
    if (lane == 0) {
        const float acc = v[3], om = 1.0f - acc;
        float* o = out + (size_t)ray * 16;
        o[0] = v[0] + bkgd[0] * om;
        o[1] = v[1] + bkgd[1] * om;
        o[2] = v[2] + bkgd[2] * om;
        o[3] = v[4];
        o[4] = acc;
        o[5] = fmaf(v[5], dirs[0], acc * origins[0]);
        o[6] = fmaf(v[5], dirs[1], acc * origins[1]);
        o[7] = fmaf(v[5], dirs[2], acc * origins[2]);
    }
}

// ===========================================================================
// Streaming inverse-CDF + merge (unchanged, passing since R3).
// ===========================================================================
__global__ void __launch_bounds__(256) sample_kernel(
    const float* __restrict__ nearp, const float* __restrict__ farp)
{
    const int ray = blockIdx.x * blockDim.x + threadIdx.x;
    if (ray >= RAYS) return;
    const float nb = nearp[ray], fb = farp[ray];
    const float* gw = g_w + ray * NCS;

    float wsum = 0.0f;
#pragma unroll
    for (int j = 0; j < 62; ++j) wsum += gw[1 + j];
    const float pad = fmaxf(1e-5f - wsum, 0.0f);
    const float padd = pad * (1.0f / 62.0f);
    const float inv = 1.0f / (wsum + pad);

#define TVAL(idx) (nb * (1.0f - (float)(idx) * (1.0f/63.0f)) + fb * ((float)(idx) * (1.0f/63.0f)))
#define BINV(idx) (0.5f * (TVAL(idx) + TVAL((idx)+1)))

    int k = 0;
    float run = (gw[1] + padd) * inv;
    float c0 = 0.0f, c1 = fminf(run, 1.0f);

    const float du = (1.0f - 1.1920929e-7f) * (1.0f / 127.0f);
    float* zout = g_z + (size_t)ray * NTS;
    int a = 0, b = 0;
    float zb = 0.0f;
    bool zb_valid = false;
    for (int m = 0; m < NTS; ++m) {
        float tb;
        if (b < NFS) {
            if (!zb_valid) {
                const float u = (float)b * du;
                while (k < 61 && c1 <= u) {
                    c0 = c1; ++k;
                    if (k <= 60) { run += (gw[1 + k] + padd) * inv; c1 = fminf(run, 1.0f); }
                    else c1 = 1.0f;
                }
                float tt = (u - c0) / (c1 - c0);
                tt = fminf(fmaxf(tt, 0.0f), 1.0f);
                const float b0v = BINV(k), b1v = BINV(k + 1);
                zb = b0v + tt * (b1v - b0v);
                zb_valid = true;
            }
            tb = zb;
        } else tb = 3.4e38f;
        const float ta = (a < NCS) ? TVAL(a) : 3.4e38f;
        if (ta <= tb) { zout[m] = ta; ++a; }
        else          { zout[m] = tb; ++b; zb_valid = false; }
    }
#undef TVAL
#undef BINV
}

// ===========================================================================
// Fine render: warp/ray, 6 samples/lane.
// ===========================================================================
__global__ void __launch_bounds__(256) fine_render(
    const float* __restrict__ origins, const float* __restrict__ dirs,
    const float* __restrict__ bkgd, float* __restrict__ out)
{
    const int lane = threadIdx.x & 31;
    const int ray = blockIdx.x * 8 + (threadIdx.x >> 5);
    const float4* sc = g_rgbd + RAYS * NCS + (size_t)ray * NTS;
    const float* zr = g_z + (size_t)ray * NTS;
    const int j0 = lane * 6;

    const float dx = dirs[3 * ray + 0], dy = dirs[3 * ray + 1], dz = dirs[3 * ray + 2];
    const float dn = sqrtf(dx * dx + dy * dy + dz * dz);

    float z[7];
#pragma unroll
    for (int s = 0; s < 6; ++s) z[s] = zr[j0 + s];
    z[6] = (lane == 31) ? 0.0f : zr[j0 + 6];

    float dd[6], pre[6];
    float running = 0.0f;
#pragma unroll
    for (int s = 0; s < 6; ++s) {
        const float td = (lane == 31 && s == 5) ? 1e10f : (z[s + 1] - z[s]);
        dd[s] = sc[j0 + s].w * td * dn;
        running += dd[s];
        pre[s] = running;
    }

    float ssum = pre[5];
#pragma unroll
    for (int off = 1; off < 32; off <<= 1) {
        float n = __shfl_up_sync(0xffffffffu, ssum, off);
        if (lane >= off) ssum += n;
    }
    const float prev = __shfl_up_sync(0xffffffffu, ssum, 1);
    const float base = (lane == 0) ? 0.0f : prev;

    float v[6] = {0.0f, 0.0f, 0.0f, 0.0f, 0.0f, 0.0f};
#pragma unroll
    for (int s = 0; s < 6; ++s) {
        const float excl = base + ((s == 0) ? 0.0f : pre[s - 1]);
        const float w = (1.0f - __expf(-dd[s])) * __expf(-excl);
        const float4 q = sc[j0 + s];
        v[0] = fmaf(w, q.x, v[0]);
        v[1] = fmaf(w, q.y, v[1]);
        v[2] = fmaf(w, q.z, v[2]);
        v[3] += w;
        v[4] = fmaf(w, z[s], v[4]);
        v[5] = fmaf(w, g_z[j0 + s], v[5]);   // ray-0 z (pts1 quirk)
    }
#pragma unroll
    for (int q = 0; q < 6; ++q) {
#pragma unroll
        for (int off = 16; off >= 1; off >>= 1)
            v[q] += __shfl_xor_sync(0xffffffffu, v[q], off);
    }
    if (lane == 0) {
        const float acc = v[3], om = 1.0f - acc;
        float* o = out + (size_t)ray * 16;
        o[8]  = v[0] + bkgd[0] * om;
        o[9]  = v[1] + bkgd[1] * om;
        o[10] = v[2] + bkgd[2] * om;
        o[11] = v[4];
        o[12] = acc;
        o[13] = fmaf(v[5], dirs[0], acc * origins[0]);
        o[14] = fmaf(v[5], dirs[1], acc * origins[1]);
        o[15] = fmaf(v[5], dirs[2], acc * origins[2]);
    }
}

// ===========================================================================
extern "C" void kernel_launch(void* const* d_in, const int* in_sizes, int n_in,
                              void* d_out, int out_size)
{
    (void)in_sizes; (void)n_in; (void)out_size;
    const float* origins = (const float*)d_in[0];
    const float* dirs    = (const float*)d_in[1];
    const float* nearp   = (const float*)d_in[2];
    const float* farp    = (const float*)d_in[3];
    const float* bkgd    = (const float*)d_in[4];
    const float* w1c = (const float*)d_in[5];
    const float* b1c = (const float*)d_in[6];
    const float* w2c = (const float*)d_in[7];
    const float* b2c = (const float*)d_in[8];
    const float* wrc = (const float*)d_in[9];
    const float* brc = (const float*)d_in[10];
    const float* wdc = (const float*)d_in[11];
    const float* bdc = (const float*)d_in[12];
    const float* w1f = (const float*)d_in[13];
    const float* b1f = (const float*)d_in[14];
    const float* w2f = (const float*)d_in[15];
    const float* b2f = (const float*)d_in[16];
    const float* wrf = (const float*)d_in[17];
    const float* brf = (const float*)d_in[18];
    const float* wdf = (const float*)d_in[19];
    const float* bdf = (const float*)d_in[20];
    float* out = (float*)d_out;

    cudaFuncSetAttribute(mlp_kernel, cudaFuncAttributeMaxDynamicSharedMemorySize, DYN_SMEM);

    float4* scratch;
    cudaGetSymbolAddress((void**)&scratch, g_rgbd);

    const int wt_coarse = RAYS * NCS / 32;    // 32768 warp-tiles
    const int wt_fine   = RAYS * NTS / 32;    // 98304 warp-tiles

    mlp_kernel<<<148, BLK, DYN_SMEM>>>(0, wt_coarse, origins, dirs, nearp, farp,
                                       w1c, b1c, w2c, b2c, wrc, brc, wdc, bdc, scratch);
    coarse_render<<<RAYS / 8, 256>>>(origins, dirs, nearp, farp, bkgd, out);
    sample_kernel<<<RAYS / 256, 256>>>(nearp, farp);
    mlp_kernel<<<148, BLK, DYN_SMEM>>>(1, wt_fine, origins, dirs, nearp, farp,
                                       w1f, b1f, w2f, b2f, wrf, brf, wdf, bdf,
                                       scratch + RAYS * NCS);
    fine_render<<<RAYS / 8, 256>>>(origins, dirs, bkgd, out);
}

// round 8
// speedup vs baseline: 3.2901x; 1.3885x over previous
#include <cuda_runtime.h>
#include <cuda_bf16.h>
#include <cstdint>

#define RAYS 16384
#define NCS 64
#define NFS 128
#define NTS 192

#define WPB 8                        // warps per block
#define BLK (WPB * 32)
#define HROW 160                     // weight row pitch (bytes); 40 words -> conflict-free lds64

__device__ float g_w[RAYS * NCS];                 // coarse weights
__device__ float g_z[RAYS * NTS];                 // merged z_vals
__device__ float4 g_rgbd[RAYS * (NCS + NTS)];     // per-point {r,g,b,density}

// ===========================================================================
// helpers
// ===========================================================================
__device__ __forceinline__ uint32_t smem_u32(const void* p) {
    uint32_t a;
    asm("{ .reg .u64 t; cvta.to.shared.u64 t, %1; cvt.u32.u64 %0, t; }" : "=r"(a) : "l"(p));
    return a;
}
__device__ __forceinline__ void lds64(uint32_t a, uint32_t& x, uint32_t& y) {
    asm volatile("ld.shared.v2.b32 {%0, %1}, [%2];" : "=r"(x), "=r"(y) : "r"(a));
}
__device__ __forceinline__ void mma16816(float* c, const uint32_t* a, uint32_t b0, uint32_t b1) {
    asm volatile(
        "mma.sync.aligned.m16n8k16.row.col.f32.bf16.bf16.f32 "
        "{%0, %1, %2, %3}, {%4, %5, %6, %7}, {%8, %9}, {%0, %1, %2, %3};"
        : "+f"(c[0]), "+f"(c[1]), "+f"(c[2]), "+f"(c[3])
        : "r"(a[0]), "r"(a[1]), "r"(a[2]), "r"(a[3]), "r"(b0), "r"(b1));
}
__device__ __forceinline__ uint32_t bf16x2_rn(float f0, float f1) {
    uint32_t r;
    asm("cvt.rn.bf16x2.f32 %0, %1, %2;" : "=r"(r) : "f"(f1), "f"(f0));
    return r;
}
__device__ __forceinline__ void split2(float f0, float f1, uint32_t& hi, uint32_t& lo) {
    hi = bf16x2_rn(f0, f1);
    const float r0 = __uint_as_float(hi << 16);
    const float r1 = __uint_as_float(hi & 0xffff0000u);
    lo = bf16x2_rn(f0 - r0, f1 - r1);
}
// permuted B-weight byte offset within a row (lane's two fragment regs adjacent)
__device__ __forceinline__ uint32_t bperm_off(int k) {
    const int kt = k >> 4, r = k & 15;
    return (uint32_t)(kt * 32 + ((r & 7) >> 1) * 8 + (r >> 3) * 4 + (r & 1) * 2);
}

// ===========================================================================
// Batched MLP via mma.sync bf16 (split-3, fp32 accum).
// 256 threads = 8 warps; each warp owns 64 points (one ray) per iteration.
// Layer1 computed DIRECTLY in A-fragment layout (no staging smem).
// mode 0: coarse (t from near/far); mode 1: fine (t from g_z).
// ===========================================================================
__global__ void __launch_bounds__(BLK, 1) mlp_kernel(
    int mode, int wtotal,
    const float* __restrict__ origins, const float* __restrict__ dirs,
    const float* __restrict__ nearp, const float* __restrict__ farp,
    const float* __restrict__ W1, const float* __restrict__ B1,
    const float* __restrict__ W2, const float* __restrict__ B2,
    const float* __restrict__ WR, const float* __restrict__ BR,
    const float* __restrict__ WD, const float* __restrict__ BD,
    float4* __restrict__ outp)
{
    __shared__ __align__(16) char sW2H[64 * HROW];   // W2^T [n][perm k] bf16
    __shared__ __align__(16) char sW2L[64 * HROW];
    __shared__ __align__(16) char sW3H[8 * HROW];    // [rgb,d,0..0][perm k]
    __shared__ __align__(16) char sW3L[8 * HROW];
    __shared__ __align__(16) float4 sW14[64];        // {w1x, w1y, w1z, b1}
    __shared__ float sB2[64];
    __shared__ float sBRD[4];
    __shared__ __align__(16) float sOut[WPB][64][4];

    const int tid = threadIdx.x;
    const int warp = tid >> 5;
    const int lane = tid & 31;

    // ---- stage weights (permuted k layout, pitch 160) ----
    for (int e = tid; e < 4096; e += BLK) {
        const int n = e >> 6, k = e & 63;
        const float w = W2[k * 64 + n];
        const __nv_bfloat16 hb = __float2bfloat16(w);
        const uint32_t off = (uint32_t)n * HROW + bperm_off(k);
        *(__nv_bfloat16*)(sW2H + off) = hb;
        *(__nv_bfloat16*)(sW2L + off) = __float2bfloat16(w - __bfloat162float(hb));
    }
    for (int e = tid; e < 512; e += BLK) {
        const int n = e >> 6, k = e & 63;
        const float w = (n < 3) ? WR[k * 3 + n] : ((n == 3) ? WD[k] : 0.0f);
        const __nv_bfloat16 hb = __float2bfloat16(w);
        const uint32_t off = (uint32_t)n * HROW + bperm_off(k);
        *(__nv_bfloat16*)(sW3H + off) = hb;
        *(__nv_bfloat16*)(sW3L + off) = __float2bfloat16(w - __bfloat162float(hb));
    }
    for (int e = tid; e < 64; e += BLK) {
        sW14[e] = make_float4(W1[e], W1[64 + e], W1[128 + e], B1[e]);
        sB2[e] = B2[e];
    }
    if (tid < 3) sBRD[tid] = BR[tid];
    if (tid == 3) sBRD[3] = BD[0];
    __syncthreads();

    const uint32_t w2hB = smem_u32(sW2H);
    const uint32_t w2lB = smem_u32(sW2L);
    const uint32_t w3hB = smem_u32(sW3H);
    const uint32_t w3lB = smem_u32(sW3L);

    const int g = lane >> 2;
    const int j0 = (lane & 3) * 2;
    const uint32_t bOff = (uint32_t)g * HROW + (uint32_t)(lane & 3) * 8;

    for (int wt = blockIdx.x * WPB + warp; wt < wtotal; wt += gridDim.x * WPB) {
        // ---- ray (one per 64-point tile) + per-lane t values ----
        const int ray = (mode == 0) ? wt : (wt / 3);
        const float ox = origins[3 * ray + 0], oy = origins[3 * ray + 1], oz = origins[3 * ray + 2];
        const float dx = dirs[3 * ray + 0], dy = dirs[3 * ray + 1], dz = dirs[3 * ray + 2];
        float tv[8];
        if (mode == 0) {
            const float nb = nearp[ray], fb = farp[ray];
#pragma unroll
            for (int a = 0; a < 8; ++a) {
                const float u = (float)(8 * a + g) * (1.0f / 63.0f);
                tv[a] = nb * (1.0f - u) + fb * u;
            }
        } else {
#pragma unroll
            for (int a = 0; a < 8; ++a)
                tv[a] = g_z[wt * 64 + 8 * a + g];
        }

        float C[4][8][4];
#pragma unroll
        for (int mt = 0; mt < 4; ++mt)
#pragma unroll
            for (int nt = 0; nt < 8; ++nt)
#pragma unroll
                for (int q = 0; q < 4; ++q) C[mt][nt][q] = 0.0f;

        // ---- layer1 fragment-direct + layer2 MMA ----
#pragma unroll
        for (int kt = 0; kt < 4; ++kt) {
            const int c0 = kt * 16 + j0;
            const float4 wa = sW14[c0], wb = sW14[c0 + 1];
            const float4 wc = sW14[c0 + 8], wd = sW14[c0 + 9];

            uint32_t Ah[4][4], Al[4][4];
#pragma unroll
            for (int mt = 0; mt < 4; ++mt) {
                const float t0 = tv[2 * mt], t1 = tv[2 * mt + 1];
                const float px0 = fmaf(t0, dx, ox), py0 = fmaf(t0, dy, oy), pz0 = fmaf(t0, dz, oz);
                const float px1 = fmaf(t1, dx, ox), py1 = fmaf(t1, dy, oy), pz1 = fmaf(t1, dz, oz);
                const float v00 = fmaxf(fmaf(px0, wa.x, fmaf(py0, wa.y, fmaf(pz0, wa.z, wa.w))), 0.0f);
                const float v01 = fmaxf(fmaf(px0, wb.x, fmaf(py0, wb.y, fmaf(pz0, wb.z, wb.w))), 0.0f);
                const float v02 = fmaxf(fmaf(px0, wc.x, fmaf(py0, wc.y, fmaf(pz0, wc.z, wc.w))), 0.0f);
                const float v03 = fmaxf(fmaf(px0, wd.x, fmaf(py0, wd.y, fmaf(pz0, wd.z, wd.w))), 0.0f);
                const float v10 = fmaxf(fmaf(px1, wa.x, fmaf(py1, wa.y, fmaf(pz1, wa.z, wa.w))), 0.0f);
                const float v11 = fmaxf(fmaf(px1, wb.x, fmaf(py1, wb.y, fmaf(pz1, wb.z, wb.w))), 0.0f);
                const float v12 = fmaxf(fmaf(px1, wc.x, fmaf(py1, wc.y, fmaf(pz1, wc.z, wc.w))), 0.0f);
                const float v13 = fmaxf(fmaf(px1, wd.x, fmaf(py1, wd.y, fmaf(pz1, wd.z, wd.w))), 0.0f);
                split2(v00, v01, Ah[mt][0], Al[mt][0]);
                split2(v10, v11, Ah[mt][1], Al[mt][1]);
                split2(v02, v03, Ah[mt][2], Al[mt][2]);
                split2(v12, v13, Ah[mt][3], Al[mt][3]);
            }
#pragma unroll
            for (int hf = 0; hf < 2; ++hf) {
                uint32_t bh[4][2], bl[4][2];
#pragma unroll
                for (int n4 = 0; n4 < 4; ++n4) {
                    const uint32_t ba = (uint32_t)(hf * 4 + n4) * (8 * HROW) + bOff + kt * 32;
                    lds64(w2hB + ba, bh[n4][0], bh[n4][1]);
                    lds64(w2lB + ba, bl[n4][0], bl[n4][1]);
                }
#pragma unroll
                for (int mt = 0; mt < 4; ++mt)
#pragma unroll
                    for (int n4 = 0; n4 < 4; ++n4) {
                        float* Cp = C[mt][hf * 4 + n4];
                        mma16816(Cp, Ah[mt], bh[n4][0], bh[n4][1]);
                        mma16816(Cp, Ah[mt], bl[n4][0], bl[n4][1]);
                        mma16816(Cp, Al[mt], bh[n4][0], bh[n4][1]);
                    }
            }
        }

        // ---- layer3: A3 repacked straight from C regs ----
        float C3[4][4];
#pragma unroll
        for (int mt = 0; mt < 4; ++mt)
#pragma unroll
            for (int q = 0; q < 4; ++q) C3[mt][q] = 0.0f;

#pragma unroll
        for (int kt = 0; kt < 4; ++kt) {
            const int nt0 = 2 * kt, nt1 = 2 * kt + 1;
            const float b00 = sB2[nt0 * 8 + j0], b01 = sB2[nt0 * 8 + j0 + 1];
            const float b10 = sB2[nt1 * 8 + j0], b11 = sB2[nt1 * 8 + j0 + 1];
            uint32_t b3h0, b3h1, b3l0, b3l1;
            lds64(w3hB + bOff + kt * 32, b3h0, b3h1);
            lds64(w3lB + bOff + kt * 32, b3l0, b3l1);
#pragma unroll
            for (int mt = 0; mt < 4; ++mt) {
                const float v00 = fmaxf(C[mt][nt0][0] + b00, 0.0f);
                const float v01 = fmaxf(C[mt][nt0][1] + b01, 0.0f);
                const float v02 = fmaxf(C[mt][nt0][2] + b00, 0.0f);
                const float v03 = fmaxf(C[mt][nt0][3] + b01, 0.0f);
                const float v10 = fmaxf(C[mt][nt1][0] + b10, 0.0f);
                const float v11 = fmaxf(C[mt][nt1][1] + b11, 0.0f);
                const float v12 = fmaxf(C[mt][nt1][2] + b10, 0.0f);
                const float v13 = fmaxf(C[mt][nt1][3] + b11, 0.0f);
                uint32_t A3h[4], A3l[4];
                split2(v00, v01, A3h[0], A3l[0]);
                split2(v02, v03, A3h[1], A3l[1]);
                split2(v10, v11, A3h[2], A3l[2]);
                split2(v12, v13, A3h[3], A3l[3]);
                mma16816(C3[mt], A3h, b3h0, b3h1);
                mma16816(C3[mt], A3h, b3l0, b3l1);
                mma16816(C3[mt], A3l, b3h0, b3h1);
            }
        }

        // ---- transpose via sOut, activate, store ----
        if ((lane & 3) < 2) {
#pragma unroll
            for (int mt = 0; mt < 4; ++mt) {
                const int r0 = mt * 16 + g;
                *(float2*)&sOut[warp][r0][j0] = make_float2(C3[mt][0], C3[mt][1]);
                *(float2*)&sOut[warp][r0 + 8][j0] = make_float2(C3[mt][2], C3[mt][3]);
            }
        }
        __syncwarp();
#pragma unroll
        for (int h = 0; h < 2; ++h) {
            const int row = h * 32 + lane;
            const float4 o4 = *(const float4*)&sOut[warp][row][0];
            const float lr = o4.x + sBRD[0];
            const float lg = o4.y + sBRD[1];
            const float lb = o4.z + sBRD[2];
            const float ld = o4.w + sBRD[3];
            outp[wt * 64 + row] = make_float4(1.0f / (1.0f + __expf(-lr)),
                                             1.0f / (1.0f + __expf(-lg)),
                                             1.0f / (1.0f + __expf(-lb)),
                                             fmaxf(ld, 0.0f));
        }
        __syncwarp();
    }
}

// ===========================================================================
// Coarse render: warp/ray, 2 samples/lane.
// ===========================================================================
__global__ void __launch_bounds__(256) coarse_render(
    const float* __restrict__ origins, const float* __restrict__ dirs,
    const float* __restrict__ nearp, const float* __restrict__ farp,
    const float* __restrict__ bkgd, float* __restrict__ out)
{
    const int lane = threadIdx.x & 31;
    const int ray = blockIdx.x * 8 + (threadIdx.x >> 5);
    const int i0 = 2 * lane, i1 = 2 * lane + 1;

    const float nb = nearp[ray], fb = farp[ray];
    const float ti0 = (float)i0 * (1.0f / 63.0f);
    const float ti1 = (float)i1 * (1.0f / 63.0f);
    const float ti2 = (float)(i1 + 1) * (1.0f / 63.0f);
    const float t0 = nb * (1.0f - ti0) + fb * ti0;
    const float t1 = nb * (1.0f - ti1) + fb * ti1;
    const float t2 = nb * (1.0f - ti2) + fb * ti2;

    const float dx = dirs[3 * ray + 0], dy = dirs[3 * ray + 1], dz = dirs[3 * ray + 2];
    const float dn = sqrtf(dx * dx + dy * dy + dz * dz);

    const float4 q0 = g_rgbd[ray * NCS + i0];
    const float4 q1 = g_rgbd[ray * NCS + i1];
    const float dd0 = q0.w * (t1 - t0) * dn;
    const float dd1 = q1.w * ((i1 == 63) ? 1e10f : (t2 - t1)) * dn;

    float s = dd0 + dd1;
#pragma unroll
    for (int off = 1; off < 32; off <<= 1) {
        float n = __shfl_up_sync(0xffffffffu, s, off);
        if (lane >= off) s += n;
    }
    const float prev = __shfl_up_sync(0xffffffffu, s, 1);
    const float excl = (lane == 0) ? 0.0f : prev;

    const float w0 = (1.0f - __expf(-dd0)) * __expf(-excl);
    const float w1 = (1.0f - __expf(-dd1)) * __expf(-(excl + dd0));
    {
        unsigned long long pk;
        asm("mov.b64 %0, {%1, %2};" : "=l"(pk) : "f"(w0), "f"(w1));
        reinterpret_cast<unsigned long long*>(g_w)[ray * 32 + lane] = pk;
    }

    const float n0 = nearp[0], f0 = farp[0];
    const float t00 = n0 * (1.0f - ti0) + f0 * ti0;
    const float t01 = n0 * (1.0f - ti1) + f0 * ti1;

    float v[6] = { fmaf(w0, q0.x, w1 * q1.x), fmaf(w0, q0.y, w1 * q1.y),
                   fmaf(w0, q0.z, w1 * q1.z), w0 + w1,
                   fmaf(w0, t0, w1 * t1), fmaf(w0, t00, w1 * t01) };
#pragma unroll
    for (int q = 0; q < 6; ++q) {
#pragma unroll
        for (int off = 16; off >= 1; off >>= 1)
            v[q] += __shfl_xor_sync(0xffffffffu, v[q], off);
    }
    if (lane == 0) {
        const float acc = v[3], om = 1.0f - acc;
        float* o = out + (size_t)ray * 16;
        o[0] = v[0] + bkgd[0] * om;
        o[1] = v[1] + bkgd[1] * om;
        o[2] = v[2] + bkgd[2] * om;
        o[3] = v[4];
        o[4] = acc;
        o[5] = fmaf(v[5], dirs[0], acc * origins[0]);
        o[6] = fmaf(v[5], dirs[1], acc * origins[1]);
        o[7] = fmaf(v[5], dirs[2], acc * origins[2]);
    }
}

// ===========================================================================
// Parallel inverse-CDF + rank-merge: warp per ray.
// ===========================================================================
#define TVAL(idx) (nb * (1.0f - (float)(idx) * (1.0f/63.0f)) + fb * ((float)(idx) * (1.0f/63.0f)))
#define BINV(idx) (0.5f * (TVAL(idx) + TVAL((idx)+1)))

__global__ void __launch_bounds__(256) sample_kernel(
    const float* __restrict__ nearp, const float* __restrict__ farp)
{
    __shared__ float scdf[8][64];
    __shared__ float szs[8][128];
    const int warp = threadIdx.x >> 5;
    const int lane = threadIdx.x & 31;
    const int ray = blockIdx.x * 8 + warp;
    const float nb = nearp[ray], fb = farp[ray];
    const float* gw = g_w + ray * NCS;

    // weights w[1..62]: lane holds w[1+lane] and (lane<30) w[33+lane]
    const float wA = gw[1 + lane];
    const float wB = (lane < 30) ? gw[33 + lane] : 0.0f;
    float tsum = wA + wB;
#pragma unroll
    for (int off = 16; off >= 1; off >>= 1)
        tsum += __shfl_xor_sync(0xffffffffu, tsum, off);
    const float pad = fmaxf(1e-5f - tsum, 0.0f);
    const float padd = pad * (1.0f / 62.0f);
    const float inv = 1.0f / (tsum + pad);
    const float pA = (wA + padd) * inv;
    const float pB = (wB + padd) * inv;

    // inclusive scans: cdf[1..32] from pA, cdf[33..61] from pB
    float s1 = pA, s2 = pB;
#pragma unroll
    for (int off = 1; off < 32; off <<= 1) {
        float n1 = __shfl_up_sync(0xffffffffu, s1, off);
        float n2 = __shfl_up_sync(0xffffffffu, s2, off);
        if (lane >= off) { s1 += n1; s2 += n2; }
    }
    const float T1 = __shfl_sync(0xffffffffu, s1, 31);
    if (lane == 0) scdf[warp][0] = 0.0f;
    scdf[warp][1 + lane] = fminf(s1, 1.0f);
    if (lane < 29) scdf[warp][33 + lane] = fminf(T1 + s2, 1.0f);
    if (lane == 31) scdf[warp][62] = 1.0f;
    __syncwarp();

    const float* cdf = scdf[warp];
    const float du = (1.0f - 1.1920929e-7f) * (1.0f / 127.0f);
    float zloc[4];
#pragma unroll
    for (int s = 0; s < 4; ++s) {
        const int sidx = lane * 4 + s;
        const float u = (float)sidx * du;
        int k = 0;
#pragma unroll
        for (int st = 32; st >= 1; st >>= 1)
            if (k + st <= 61 && cdf[k + st] <= u) k += st;
        const float c0 = cdf[k], c1 = cdf[k + 1];
        float tt = (u - c0) / (c1 - c0);
        tt = fminf(fmaxf(tt, 0.0f), 1.0f);
        const float b0 = BINV(k), b1 = BINV(k + 1);
        zloc[s] = b0 + tt * (b1 - b0);
        szs[warp][sidx] = zloc[s];
    }
    __syncwarp();

    float* zout = g_z + (size_t)ray * NTS;
    // scatter z samples: pos = sidx + #{t_i <= z}
#pragma unroll
    for (int s = 0; s < 4; ++s) {
        const int sidx = lane * 4 + s;
        const float z = zloc[s];
        int i0 = (int)floorf((z - nb) / (fb - nb) * 63.0f);
        i0 = max(-1, min(63, i0));
        while (i0 + 1 <= 63 && TVAL(i0 + 1) <= z) ++i0;
        while (i0 >= 0 && TVAL(i0) > z) --i0;
        zout[sidx + i0 + 1] = z;
    }
    // scatter t_vals: pos = i + #{z < t}
#pragma unroll
    for (int r = 0; r < 2; ++r) {
        const int i = lane * 2 + r;
        const float tvv = TVAL(i);
        int c = 0;
#pragma unroll
        for (int st = 128; st >= 1; st >>= 1)
            if (c + st <= 128 && szs[warp][c + st - 1] < tvv) c += st;
        zout[i + c] = tvv;
    }
}
#undef TVAL
#undef BINV

// ===========================================================================
// Fine render: warp/ray, 6 samples/lane.
// ===========================================================================
__global__ void __launch_bounds__(256) fine_render(
    const float* __restrict__ origins, const float* __restrict__ dirs,
    const float* __restrict__ bkgd, float* __restrict__ out)
{
    const int lane = threadIdx.x & 31;
    const int ray = blockIdx.x * 8 + (threadIdx.x >> 5);
    const float4* sc = g_rgbd + RAYS * NCS + (size_t)ray * NTS;
    const float* zr = g_z + (size_t)ray * NTS;
    const int j0 = lane * 6;

    const float dx = dirs[3 * ray + 0], dy = dirs[3 * ray + 1], dz = dirs[3 * ray + 2];
    const float dn = sqrtf(dx * dx + dy * dy + dz * dz);

    float z[7];
#pragma unroll
    for (int s = 0; s < 6; ++s) z[s] = zr[j0 + s];
    z[6] = (lane == 31) ? 0.0f : zr[j0 + 6];

    float dd[6], pre[6];
    float running = 0.0f;
#pragma unroll
    for (int s = 0; s < 6; ++s) {
        const float td = (lane == 31 && s == 5) ? 1e10f : (z[s + 1] - z[s]);
        dd[s] = sc[j0 + s].w * td * dn;
        running += dd[s];
        pre[s] = running;
    }

    float ssum = pre[5];
#pragma unroll
    for (int off = 1; off < 32; off <<= 1) {
        float n = __shfl_up_sync(0xffffffffu, ssum, off);
        if (lane >= off) ssum += n;
    }
    const float prev = __shfl_up_sync(0xffffffffu, ssum, 1);
    const float base = (lane == 0) ? 0.0f : prev;

    float v[6] = {0.0f, 0.0f, 0.0f, 0.0f, 0.0f, 0.0f};
#pragma unroll
    for (int s = 0; s < 6; ++s) {
        const float excl = base + ((s == 0) ? 0.0f : pre[s - 1]);
        const float w = (1.0f - __expf(-dd[s])) * __expf(-excl);
        const float4 q = sc[j0 + s];
        v[0] = fmaf(w, q.x, v[0]);
        v[1] = fmaf(w, q.y, v[1]);
        v[2] = fmaf(w, q.z, v[2]);
        v[3] += w;
        v[4] = fmaf(w, z[s], v[4]);
        v[5] = fmaf(w, g_z[j0 + s], v[5]);   // ray-0 z (pts1 quirk)
    }
#pragma unroll
    for (int q = 0; q < 6; ++q) {
#pragma unroll
        for (int off = 16; off >= 1; off >>= 1)
            v[q] += __shfl_xor_sync(0xffffffffu, v[q], off);
    }
    if (lane == 0) {
        const float acc = v[3], om = 1.0f - acc;
        float* o = out + (size_t)ray * 16;
        o[8]  = v[0] + bkgd[0] * om;
        o[9]  = v[1] + bkgd[1] * om;
        o[10] = v[2] + bkgd[2] * om;
        o[11] = v[4];
        o[12] = acc;
        o[13] = fmaf(v[5], dirs[0], acc * origins[0]);
        o[14] = fmaf(v[5], dirs[1], acc * origins[1]);
        o[15] = fmaf(v[5], dirs[2], acc * origins[2]);
    }
}

// ===========================================================================
extern "C" void kernel_launch(void* const* d_in, const int* in_sizes, int n_in,
                              void* d_out, int out_size)
{
    (void)in_sizes; (void)n_in; (void)out_size;
    const float* origins = (const float*)d_in[0];
    const float* dirs    = (const float*)d_in[1];
    const float* nearp   = (const float*)d_in[2];
    const float* farp    = (const float*)d_in[3];
    const float* bkgd    = (const float*)d_in[4];
    const float* w1c = (const float*)d_in[5];
    const float* b1c = (const float*)d_in[6];
    const float* w2c = (const float*)d_in[7];
    const float* b2c = (const float*)d_in[8];
    const float* wrc = (const float*)d_in[9];
    const float* brc = (const float*)d_in[10];
    const float* wdc = (const float*)d_in[11];
    const float* bdc = (const float*)d_in[12];
    const float* w1f = (const float*)d_in[13];
    const float* b1f = (const float*)d_in[14];
    const float* w2f = (const float*)d_in[15];
    const float* b2f = (const float*)d_in[16];
    const float* wrf = (const float*)d_in[17];
    const float* brf = (const float*)d_in[18];
    const float* wdf = (const float*)d_in[19];
    const float* bdf = (const float*)d_in[20];
    float* out = (float*)d_out;

    float4* scratch;
    cudaGetSymbolAddress((void**)&scratch, g_rgbd);

    const int wt_coarse = RAYS;               // 64 pts/tile = 1 coarse ray
    const int wt_fine   = RAYS * 3;           // 3 tiles per fine ray

    mlp_kernel<<<148, BLK>>>(0, wt_coarse, origins, dirs, nearp, farp,
                             w1c, b1c, w2c, b2c, wrc, brc, wdc, bdc, scratch);
    coarse_render<<<RAYS / 8, 256>>>(origins, dirs, nearp, farp, bkgd, out);
    sample_kernel<<<RAYS / 8, 256>>>(nearp, farp);
    mlp_kernel<<<148, BLK>>>(1, wt_fine, origins, dirs, nearp, farp,
                             w1f, b1f, w2f, b2f, wrf, brf, wdf, bdf,
                             scratch + RAYS * NCS);
    fine_render<<<RAYS / 8, 256>>>(origins, dirs, bkgd, out);
}

// round 9
// speedup vs baseline: 3.4590x; 1.0513x over previous
#include <cuda_runtime.h>
#include <cuda_bf16.h>
#include <cstdint>

#define RAYS 16384
#define NCS 64
#define NFS 128
#define NTS 192

#define WPB 8                        // warps per block
#define BLK (WPB * 32)
#define MT 2                         // m16 tiles per warp (32 points)
#define HROW 160                     // weight row pitch (bytes); conflict-free lds64

__device__ float g_w[RAYS * NCS];                 // coarse weights
__device__ float g_z[RAYS * NTS];                 // merged z_vals
__device__ float4 g_rgbd[RAYS * (NCS + NTS)];     // per-point {r,g,b,density}

// ===========================================================================
// helpers
// ===========================================================================
__device__ __forceinline__ uint32_t smem_u32(const void* p) {
    uint32_t a;
    asm("{ .reg .u64 t; cvta.to.shared.u64 t, %1; cvt.u32.u64 %0, t; }" : "=r"(a) : "l"(p));
    return a;
}
__device__ __forceinline__ void lds64(uint32_t a, uint32_t& x, uint32_t& y) {
    asm volatile("ld.shared.v2.b32 {%0, %1}, [%2];" : "=r"(x), "=r"(y) : "r"(a));
}
__device__ __forceinline__ void mma16816(float* c, const uint32_t* a, uint32_t b0, uint32_t b1) {
    asm volatile(
        "mma.sync.aligned.m16n8k16.row.col.f32.bf16.bf16.f32 "
        "{%0, %1, %2, %3}, {%4, %5, %6, %7}, {%8, %9}, {%0, %1, %2, %3};"
        : "+f"(c[0]), "+f"(c[1]), "+f"(c[2]), "+f"(c[3])
        : "r"(a[0]), "r"(a[1]), "r"(a[2]), "r"(a[3]), "r"(b0), "r"(b1));
}
__device__ __forceinline__ uint32_t bf16x2_rn(float f0, float f1) {
    uint32_t r;
    asm("cvt.rn.bf16x2.f32 %0, %1, %2;" : "=r"(r) : "f"(f1), "f"(f0));
    return r;
}
__device__ __forceinline__ void split2(float f0, float f1, uint32_t& hi, uint32_t& lo) {
    hi = bf16x2_rn(f0, f1);
    const float r0 = __uint_as_float(hi << 16);
    const float r1 = __uint_as_float(hi & 0xffff0000u);
    lo = bf16x2_rn(f0 - r0, f1 - r1);
}
// permuted B-weight byte offset within a row (lane's two fragment regs adjacent)
__device__ __forceinline__ uint32_t bperm_off(int k) {
    const int kt = k >> 4, r = k & 15;
    return (uint32_t)(kt * 32 + ((r & 7) >> 1) * 8 + (r >> 3) * 4 + (r & 1) * 2);
}

// ===========================================================================
// Batched MLP via mma.sync bf16 (split-3, fp32 accum).
// 256 threads = 8 warps, 2 blocks/SM; each warp owns 32 points per iter.
// Layer1 computed DIRECTLY in A-fragment layout (no staging smem).
// mode 0: coarse (t from near/far); mode 1: fine (t from g_z).
// ===========================================================================
__global__ void __launch_bounds__(BLK, 2) mlp_kernel(
    int mode, int wtotal,
    const float* __restrict__ origins, const float* __restrict__ dirs,
    const float* __restrict__ nearp, const float* __restrict__ farp,
    const float* __restrict__ W1, const float* __restrict__ B1,
    const float* __restrict__ W2, const float* __restrict__ B2,
    const float* __restrict__ WR, const float* __restrict__ BR,
    const float* __restrict__ WD, const float* __restrict__ BD,
    float4* __restrict__ outp)
{
    __shared__ __align__(16) char sW2H[64 * HROW];   // W2^T [n][perm k] bf16
    __shared__ __align__(16) char sW2L[64 * HROW];
    __shared__ __align__(16) char sW3H[8 * HROW];    // [rgb,d,0..0][perm k]
    __shared__ __align__(16) char sW3L[8 * HROW];
    __shared__ __align__(16) float4 sW14[64];        // {w1x, w1y, w1z, b1}
    __shared__ float sB2[64];
    __shared__ float sBRD[4];
    __shared__ __align__(16) float sOut[WPB][32][4];

    const int tid = threadIdx.x;
    const int warp = tid >> 5;
    const int lane = tid & 31;

    // ---- stage weights (permuted k layout) ----
    for (int e = tid; e < 4096; e += BLK) {
        const int n = e >> 6, k = e & 63;
        const float w = W2[k * 64 + n];
        const __nv_bfloat16 hb = __float2bfloat16(w);
        const uint32_t off = (uint32_t)n * HROW + bperm_off(k);
        *(__nv_bfloat16*)(sW2H + off) = hb;
        *(__nv_bfloat16*)(sW2L + off) = __float2bfloat16(w - __bfloat162float(hb));
    }
    for (int e = tid; e < 512; e += BLK) {
        const int n = e >> 6, k = e & 63;
        const float w = (n < 3) ? WR[k * 3 + n] : ((n == 3) ? WD[k] : 0.0f);
        const __nv_bfloat16 hb = __float2bfloat16(w);
        const uint32_t off = (uint32_t)n * HROW + bperm_off(k);
        *(__nv_bfloat16*)(sW3H + off) = hb;
        *(__nv_bfloat16*)(sW3L + off) = __float2bfloat16(w - __bfloat162float(hb));
    }
    for (int e = tid; e < 64; e += BLK) {
        sW14[e] = make_float4(W1[e], W1[64 + e], W1[128 + e], B1[e]);
        sB2[e] = B2[e];
    }
    if (tid < 3) sBRD[tid] = BR[tid];
    if (tid == 3) sBRD[3] = BD[0];
    __syncthreads();

    const uint32_t w2hB = smem_u32(sW2H);
    const uint32_t w2lB = smem_u32(sW2L);
    const uint32_t w3hB = smem_u32(sW3H);
    const uint32_t w3lB = smem_u32(sW3L);

    const int g = lane >> 2;
    const int j0 = (lane & 3) * 2;
    const uint32_t bOff = (uint32_t)g * HROW + (uint32_t)(lane & 3) * 8;

    for (int wt = blockIdx.x * WPB + warp; wt < wtotal; wt += gridDim.x * WPB) {
        // ---- ray + per-lane t values (tile = 32 points, within one ray) ----
        const int ray = (mode == 0) ? (wt >> 1) : (wt / 6);
        const float ox = origins[3 * ray + 0], oy = origins[3 * ray + 1], oz = origins[3 * ray + 2];
        const float dx = dirs[3 * ray + 0], dy = dirs[3 * ray + 1], dz = dirs[3 * ray + 2];
        float tv[4];
        if (mode == 0) {
            const float nb = nearp[ray], fb = farp[ray];
            const int base = (wt & 1) * 32;
#pragma unroll
            for (int a = 0; a < 4; ++a) {
                const float u = (float)(base + 8 * a + g) * (1.0f / 63.0f);
                tv[a] = nb * (1.0f - u) + fb * u;
            }
        } else {
#pragma unroll
            for (int a = 0; a < 4; ++a)
                tv[a] = g_z[wt * 32 + 8 * a + g];
        }

        float C[MT][8][4];
#pragma unroll
        for (int mt = 0; mt < MT; ++mt)
#pragma unroll
            for (int nt = 0; nt < 8; ++nt)
#pragma unroll
                for (int q = 0; q < 4; ++q) C[mt][nt][q] = 0.0f;

        // ---- layer1 fragment-direct + layer2 MMA ----
#pragma unroll
        for (int kt = 0; kt < 4; ++kt) {
            const int c0 = kt * 16 + j0;
            const float4 wa = sW14[c0], wb = sW14[c0 + 1];
            const float4 wc = sW14[c0 + 8], wd = sW14[c0 + 9];

            uint32_t Ah[MT][4], Al[MT][4];
#pragma unroll
            for (int mt = 0; mt < MT; ++mt) {
                const float t0 = tv[2 * mt], t1 = tv[2 * mt + 1];
                const float px0 = fmaf(t0, dx, ox), py0 = fmaf(t0, dy, oy), pz0 = fmaf(t0, dz, oz);
                const float px1 = fmaf(t1, dx, ox), py1 = fmaf(t1, dy, oy), pz1 = fmaf(t1, dz, oz);
                const float v00 = fmaxf(fmaf(px0, wa.x, fmaf(py0, wa.y, fmaf(pz0, wa.z, wa.w))), 0.0f);
                const float v01 = fmaxf(fmaf(px0, wb.x, fmaf(py0, wb.y, fmaf(pz0, wb.z, wb.w))), 0.0f);
                const float v02 = fmaxf(fmaf(px0, wc.x, fmaf(py0, wc.y, fmaf(pz0, wc.z, wc.w))), 0.0f);
                const float v03 = fmaxf(fmaf(px0, wd.x, fmaf(py0, wd.y, fmaf(pz0, wd.z, wd.w))), 0.0f);
                const float v10 = fmaxf(fmaf(px1, wa.x, fmaf(py1, wa.y, fmaf(pz1, wa.z, wa.w))), 0.0f);
                const float v11 = fmaxf(fmaf(px1, wb.x, fmaf(py1, wb.y, fmaf(pz1, wb.z, wb.w))), 0.0f);
                const float v12 = fmaxf(fmaf(px1, wc.x, fmaf(py1, wc.y, fmaf(pz1, wc.z, wc.w))), 0.0f);
                const float v13 = fmaxf(fmaf(px1, wd.x, fmaf(py1, wd.y, fmaf(pz1, wd.z, wd.w))), 0.0f);
                split2(v00, v01, Ah[mt][0], Al[mt][0]);
                split2(v10, v11, Ah[mt][1], Al[mt][1]);
                split2(v02, v03, Ah[mt][2], Al[mt][2]);
                split2(v12, v13, Ah[mt][3], Al[mt][3]);
            }
#pragma unroll
            for (int hf = 0; hf < 2; ++hf) {
                uint32_t bh[4][2], bl[4][2];
#pragma unroll
                for (int n4 = 0; n4 < 4; ++n4) {
                    const uint32_t ba = (uint32_t)(hf * 4 + n4) * (8 * HROW) + bOff + kt * 32;
                    lds64(w2hB + ba, bh[n4][0], bh[n4][1]);
                    lds64(w2lB + ba, bl[n4][0], bl[n4][1]);
                }
#pragma unroll
                for (int mt = 0; mt < MT; ++mt)
#pragma unroll
                    for (int n4 = 0; n4 < 4; ++n4) {
                        float* Cp = C[mt][hf * 4 + n4];
                        mma16816(Cp, Ah[mt], bh[n4][0], bh[n4][1]);
                        mma16816(Cp, Ah[mt], bl[n4][0], bl[n4][1]);
                        mma16816(Cp, Al[mt], bh[n4][0], bh[n4][1]);
                    }
            }
        }

        // ---- layer3: A3 repacked straight from C regs ----
        float C3[MT][4];
#pragma unroll
        for (int mt = 0; mt < MT; ++mt)
#pragma unroll
            for (int q = 0; q < 4; ++q) C3[mt][q] = 0.0f;

#pragma unroll
        for (int kt = 0; kt < 4; ++kt) {
            const int nt0 = 2 * kt, nt1 = 2 * kt + 1;
            const float b00 = sB2[nt0 * 8 + j0], b01 = sB2[nt0 * 8 + j0 + 1];
            const float b10 = sB2[nt1 * 8 + j0], b11 = sB2[nt1 * 8 + j0 + 1];
            uint32_t b3h0, b3h1, b3l0, b3l1;
            lds64(w3hB + bOff + kt * 32, b3h0, b3h1);
            lds64(w3lB + bOff + kt * 32, b3l0, b3l1);
#pragma unroll
            for (int mt = 0; mt < MT; ++mt) {
                const float v00 = fmaxf(C[mt][nt0][0] + b00, 0.0f);
                const float v01 = fmaxf(C[mt][nt0][1] + b01, 0.0f);
                const float v02 = fmaxf(C[mt][nt0][2] + b00, 0.0f);
                const float v03 = fmaxf(C[mt][nt0][3] + b01, 0.0f);
                const float v10 = fmaxf(C[mt][nt1][0] + b10, 0.0f);
                const float v11 = fmaxf(C[mt][nt1][1] + b11, 0.0f);
                const float v12 = fmaxf(C[mt][nt1][2] + b10, 0.0f);
                const float v13 = fmaxf(C[mt][nt1][3] + b11, 0.0f);
                uint32_t A3h[4], A3l[4];
                split2(v00, v01, A3h[0], A3l[0]);
                split2(v02, v03, A3h[1], A3l[1]);
                split2(v10, v11, A3h[2], A3l[2]);
                split2(v12, v13, A3h[3], A3l[3]);
                mma16816(C3[mt], A3h, b3h0, b3h1);
                mma16816(C3[mt], A3h, b3l0, b3l1);
                mma16816(C3[mt], A3l, b3h0, b3h1);
            }
        }

        // ---- transpose via sOut, activate, store ----
        if ((lane & 3) < 2) {
#pragma unroll
            for (int mt = 0; mt < MT; ++mt) {
                const int r0 = mt * 16 + g;
                *(float2*)&sOut[warp][r0][j0] = make_float2(C3[mt][0], C3[mt][1]);
                *(float2*)&sOut[warp][r0 + 8][j0] = make_float2(C3[mt][2], C3[mt][3]);
            }
        }
        __syncwarp();
        {
            const float4 o4 = *(const float4*)&sOut[warp][lane][0];
            const float lr = o4.x + sBRD[0];
            const float lg = o4.y + sBRD[1];
            const float lb = o4.z + sBRD[2];
            const float ld = o4.w + sBRD[3];
            outp[wt * 32 + lane] = make_float4(1.0f / (1.0f + __expf(-lr)),
                                              1.0f / (1.0f + __expf(-lg)),
                                              1.0f / (1.0f + __expf(-lb)),
                                              fmaxf(ld, 0.0f));
        }
        __syncwarp();
    }
}

// ===========================================================================
// Coarse render: warp/ray, 2 samples/lane.
// ===========================================================================
__global__ void __launch_bounds__(256) coarse_render(
    const float* __restrict__ origins, const float* __restrict__ dirs,
    const float* __restrict__ nearp, const float* __restrict__ farp,
    const float* __restrict__ bkgd, float* __restrict__ out)
{
    const int lane = threadIdx.x & 31;
    const int ray = blockIdx.x * 8 + (threadIdx.x >> 5);
    const int i0 = 2 * lane, i1 = 2 * lane + 1;

    const float nb = nearp[ray], fb = farp[ray];
    const float ti0 = (float)i0 * (1.0f / 63.0f);
    const float ti1 = (float)i1 * (1.0f / 63.0f);
    const float ti2 = (float)(i1 + 1) * (1.0f / 63.0f);
    const float t0 = nb * (1.0f - ti0) + fb * ti0;
    const float t1 = nb * (1.0f - ti1) + fb * ti1;
    const float t2 = nb * (1.0f - ti2) + fb * ti2;

    const float dx = dirs[3 * ray + 0], dy = dirs[3 * ray + 1], dz = dirs[3 * ray + 2];
    const float dn = sqrtf(dx * dx + dy * dy + dz * dz);

    const float4 q0 = g_rgbd[ray * NCS + i0];
    const float4 q1 = g_rgbd[ray * NCS + i1];
    const float dd0 = q0.w * (t1 - t0) * dn;
    const float dd1 = q1.w * ((i1 == 63) ? 1e10f : (t2 - t1)) * dn;

    float s = dd0 + dd1;
#pragma unroll
    for (int off = 1; off < 32; off <<= 1) {
        float n = __shfl_up_sync(0xffffffffu, s, off);
        if (lane >= off) s += n;
    }
    const float prev = __shfl_up_sync(0xffffffffu, s, 1);
    const float excl = (lane == 0) ? 0.0f : prev;

    const float w0 = (1.0f - __expf(-dd0)) * __expf(-excl);
    const float w1 = (1.0f - __expf(-dd1)) * __expf(-(excl + dd0));
    {
        unsigned long long pk;
        asm("mov.b64 %0, {%1, %2};" : "=l"(pk) : "f"(w0), "f"(w1));
        reinterpret_cast<unsigned long long*>(g_w)[ray * 32 + lane] = pk;
    }

    const float n0 = nearp[0], f0 = farp[0];
    const float t00 = n0 * (1.0f - ti0) + f0 * ti0;
    const float t01 = n0 * (1.0f - ti1) + f0 * ti1;

    float v[6] = { fmaf(w0, q0.x, w1 * q1.x), fmaf(w0, q0.y, w1 * q1.y),
                   fmaf(w0, q0.z, w1 * q1.z), w0 + w1,
                   fmaf(w0, t0, w1 * t1), fmaf(w0, t00, w1 * t01) };
#pragma unroll
    for (int q = 0; q < 6; ++q) {
#pragma unroll
        for (int off = 16; off >= 1; off >>= 1)
            v[q] += __shfl_xor_sync(0xffffffffu, v[q], off);
    }
    if (lane == 0) {
        const float acc = v[3], om = 1.0f - acc;
        float* o = out + (size_t)ray * 16;
        o[0] = v[0] + bkgd[0] * om;
        o[1] = v[1] + bkgd[1] * om;
        o[2] = v[2] + bkgd[2] * om;
        o[3] = v[4];
        o[4] = acc;
        o[5] = fmaf(v[5], dirs[0], acc * origins[0]);
        o[6] = fmaf(v[5], dirs[1], acc * origins[1]);
        o[7] = fmaf(v[5], dirs[2], acc * origins[2]);
    }
}

// ===========================================================================
// Parallel inverse-CDF + rank-merge: warp per ray (unchanged from R8 pass).
// ===========================================================================
#define TVAL(idx) (nb * (1.0f - (float)(idx) * (1.0f/63.0f)) + fb * ((float)(idx) * (1.0f/63.0f)))
#define BINV(idx) (0.5f * (TVAL(idx) + TVAL((idx)+1)))

__global__ void __launch_bounds__(256) sample_kernel(
    const float* __restrict__ nearp, const float* __restrict__ farp)
{
    __shared__ float scdf[8][64];
    __shared__ float szs[8][128];
    const int warp = threadIdx.x >> 5;
    const int lane = threadIdx.x & 31;
    const int ray = blockIdx.x * 8 + warp;
    const float nb = nearp[ray], fb = farp[ray];
    const float* gw = g_w + ray * NCS;

    const float wA = gw[1 + lane];
    const float wB = (lane < 30) ? gw[33 + lane] : 0.0f;
    float tsum = wA + wB;
#pragma unroll
    for (int off = 16; off >= 1; off >>= 1)
        tsum += __shfl_xor_sync(0xffffffffu, tsum, off);
    const float pad = fmaxf(1e-5f - tsum, 0.0f);
    const float padd = pad * (1.0f / 62.0f);
    const float inv = 1.0f / (tsum + pad);
    const float pA = (wA + padd) * inv;
    const float pB = (wB + padd) * inv;

    float s1 = pA, s2 = pB;
#pragma unroll
    for (int off = 1; off < 32; off <<= 1) {
        float n1 = __shfl_up_sync(0xffffffffu, s1, off);
        float n2 = __shfl_up_sync(0xffffffffu, s2, off);
        if (lane >= off) { s1 += n1; s2 += n2; }
    }
    const float T1 = __shfl_sync(0xffffffffu, s1, 31);
    if (lane == 0) scdf[warp][0] = 0.0f;
    scdf[warp][1 + lane] = fminf(s1, 1.0f);
    if (lane < 29) scdf[warp][33 + lane] = fminf(T1 + s2, 1.0f);
    if (lane == 31) scdf[warp][62] = 1.0f;
    __syncwarp();

    const float* cdf = scdf[warp];
    const float du = (1.0f - 1.1920929e-7f) * (1.0f / 127.0f);
    float zloc[4];
#pragma unroll
    for (int s = 0; s < 4; ++s) {
        const int sidx = lane * 4 + s;
        const float u = (float)sidx * du;
        int k = 0;
#pragma unroll
        for (int st = 32; st >= 1; st >>= 1)
            if (k + st <= 61 && cdf[k + st] <= u) k += st;
        const float c0 = cdf[k], c1 = cdf[k + 1];
        float tt = (u - c0) / (c1 - c0);
        tt = fminf(fmaxf(tt, 0.0f), 1.0f);
        const float b0 = BINV(k), b1 = BINV(k + 1);
        zloc[s] = b0 + tt * (b1 - b0);
        szs[warp][sidx] = zloc[s];
    }
    __syncwarp();

    float* zout = g_z + (size_t)ray * NTS;
#pragma unroll
    for (int s = 0; s < 4; ++s) {
        const int sidx = lane * 4 + s;
        const float z = zloc[s];
        int i0 = (int)floorf((z - nb) / (fb - nb) * 63.0f);
        i0 = max(-1, min(63, i0));
        while (i0 + 1 <= 63 && TVAL(i0 + 1) <= z) ++i0;
        while (i0 >= 0 && TVAL(i0) > z) --i0;
        zout[sidx + i0 + 1] = z;
    }
#pragma unroll
    for (int r = 0; r < 2; ++r) {
        const int i = lane * 2 + r;
        const float tvv = TVAL(i);
        int c = 0;
#pragma unroll
        for (int st = 128; st >= 1; st >>= 1)
            if (c + st <= 128 && szs[warp][c + st - 1] < tvv) c += st;
        zout[i + c] = tvv;
    }
}
#undef TVAL
#undef BINV

// ===========================================================================
// Fine render: warp/ray, 6 samples/lane.
// ===========================================================================
__global__ void __launch_bounds__(256) fine_render(
    const float* __restrict__ origins, const float* __restrict__ dirs,
    const float* __restrict__ bkgd, float* __restrict__ out)
{
    const int lane = threadIdx.x & 31;
    const int ray = blockIdx.x * 8 + (threadIdx.x >> 5);
    const float4* sc = g_rgbd + RAYS * NCS + (size_t)ray * NTS;
    const float* zr = g_z + (size_t)ray * NTS;
    const int j0 = lane * 6;

    const float dx = dirs[3 * ray + 0], dy = dirs[3 * ray + 1], dz = dirs[3 * ray + 2];
    const float dn = sqrtf(dx * dx + dy * dy + dz * dz);

    float z[7];
#pragma unroll
    for (int s = 0; s < 6; ++s) z[s] = zr[j0 + s];
    z[6] = (lane == 31) ? 0.0f : zr[j0 + 6];

    float dd[6], pre[6];
    float running = 0.0f;
#pragma unroll
    for (int s = 0; s < 6; ++s) {
        const float td = (lane == 31 && s == 5) ? 1e10f : (z[s + 1] - z[s]);
        dd[s] = sc[j0 + s].w * td * dn;
        running += dd[s];
        pre[s] = running;
    }

    float ssum = pre[5];
#pragma unroll
    for (int off = 1; off < 32; off <<= 1) {
        float n = __shfl_up_sync(0xffffffffu, ssum, off);
        if (lane >= off) ssum += n;
    }
    const float prev = __shfl_up_sync(0xffffffffu, ssum, 1);
    const float base = (lane == 0) ? 0.0f : prev;

    float v[6] = {0.0f, 0.0f, 0.0f, 0.0f, 0.0f, 0.0f};
#pragma unroll
    for (int s = 0; s < 6; ++s) {
        const float excl = base + ((s == 0) ? 0.0f : pre[s - 1]);
        const float w = (1.0f - __expf(-dd[s])) * __expf(-excl);
        const float4 q = sc[j0 + s];
        v[0] = fmaf(w, q.x, v[0]);
        v[1] = fmaf(w, q.y, v[1]);
        v[2] = fmaf(w, q.z, v[2]);
        v[3] += w;
        v[4] = fmaf(w, z[s], v[4]);
        v[5] = fmaf(w, g_z[j0 + s], v[5]);   // ray-0 z (pts1 quirk)
    }
#pragma unroll
    for (int q = 0; q < 6; ++q) {
#pragma unroll
        for (int off = 16; off >= 1; off >>= 1)
            v[q] += __shfl_xor_sync(0xffffffffu, v[q], off);
    }
    if (lane == 0) {
        const float acc = v[3], om = 1.0f - acc;
        float* o = out + (size_t)ray * 16;
        o[8]  = v[0] + bkgd[0] * om;
        o[9]  = v[1] + bkgd[1] * om;
        o[10] = v[2] + bkgd[2] * om;
        o[11] = v[4];
        o[12] = acc;
        o[13] = fmaf(v[5], dirs[0], acc * origins[0]);
        o[14] = fmaf(v[5], dirs[1], acc * origins[1]);
        o[15] = fmaf(v[5], dirs[2], acc * origins[2]);
    }
}

// ===========================================================================
extern "C" void kernel_launch(void* const* d_in, const int* in_sizes, int n_in,
                              void* d_out, int out_size)
{
    (void)in_sizes; (void)n_in; (void)out_size;
    const float* origins = (const float*)d_in[0];
    const float* dirs    = (const float*)d_in[1];
    const float* nearp   = (const float*)d_in[2];
    const float* farp    = (const float*)d_in[3];
    const float* bkgd    = (const float*)d_in[4];
    const float* w1c = (const float*)d_in[5];
    const float* b1c = (const float*)d_in[6];
    const float* w2c = (const float*)d_in[7];
    const float* b2c = (const float*)d_in[8];
    const float* wrc = (const float*)d_in[9];
    const float* brc = (const float*)d_in[10];
    const float* wdc = (const float*)d_in[11];
    const float* bdc = (const float*)d_in[12];
    const float* w1f = (const float*)d_in[13];
    const float* b1f = (const float*)d_in[14];
    const float* w2f = (const float*)d_in[15];
    const float* b2f = (const float*)d_in[16];
    const float* wrf = (const float*)d_in[17];
    const float* brf = (const float*)d_in[18];
    const float* wdf = (const float*)d_in[19];
    const float* bdf = (const float*)d_in[20];
    float* out = (float*)d_out;

    float4* scratch;
    cudaGetSymbolAddress((void**)&scratch, g_rgbd);

    const int wt_coarse = RAYS * 2;           // 32 pts/tile, 2 tiles per coarse ray
    const int wt_fine   = RAYS * 6;           // 6 tiles per fine ray

    mlp_kernel<<<296, BLK>>>(0, wt_coarse, origins, dirs, nearp, farp,
                             w1c, b1c, w2c, b2c, wrc, brc, wdc, bdc, scratch);
    coarse_render<<<RAYS / 8, 256>>>(origins, dirs, nearp, farp, bkgd, out);
    sample_kernel<<<RAYS / 8, 256>>>(nearp, farp);
    mlp_kernel<<<296, BLK>>>(1, wt_fine, origins, dirs, nearp, farp,
                             w1f, b1f, w2f, b2f, wrf, brf, wdf, bdf,
                             scratch + RAYS * NCS);
    fine_render<<<RAYS / 8, 256>>>(origins, dirs, bkgd, out);
}

// round 10
// speedup vs baseline: 3.4919x; 1.0095x over previous
#include <cuda_runtime.h>
#include <cuda_bf16.h>
#include <cstdint>

#define RAYS 16384
#define NCS 64
#define NFS 128
#define NTS 192

#define WPB 8                        // warps per block
#define BLK (WPB * 32)
#define MT 2                         // m16 tiles per warp (32 points)
#define HROW 160                     // weight row pitch (bytes); conflict-free lds64

__device__ float g_w[RAYS * NCS];                 // coarse weights
__device__ float g_z[RAYS * NTS];                 // merged z_vals
__device__ float4 g_rgbd[RAYS * (NCS + NTS)];     // per-point {r,g,b,density}

// ===========================================================================
// helpers
// ===========================================================================
__device__ __forceinline__ uint32_t smem_u32(const void* p) {
    uint32_t a;
    asm("{ .reg .u64 t; cvta.to.shared.u64 t, %1; cvt.u32.u64 %0, t; }" : "=r"(a) : "l"(p));
    return a;
}
__device__ __forceinline__ void lds64(uint32_t a, uint32_t& x, uint32_t& y) {
    asm volatile("ld.shared.v2.b32 {%0, %1}, [%2];" : "=r"(x), "=r"(y) : "r"(a));
}
__device__ __forceinline__ void mma16816(float* c, const uint32_t* a, uint32_t b0, uint32_t b1) {
    asm volatile(
        "mma.sync.aligned.m16n8k16.row.col.f32.bf16.bf16.f32 "
        "{%0, %1, %2, %3}, {%4, %5, %6, %7}, {%8, %9}, {%0, %1, %2, %3};"
        : "+f"(c[0]), "+f"(c[1]), "+f"(c[2]), "+f"(c[3])
        : "r"(a[0]), "r"(a[1]), "r"(a[2]), "r"(a[3]), "r"(b0), "r"(b1));
}
__device__ __forceinline__ uint32_t bf16x2_rn(float f0, float f1) {
    uint32_t r;
    asm("cvt.rn.bf16x2.f32 %0, %1, %2;" : "=r"(r) : "f"(f1), "f"(f0));
    return r;
}
__device__ __forceinline__ void split2(float f0, float f1, uint32_t& hi, uint32_t& lo) {
    hi = bf16x2_rn(f0, f1);
    const float r0 = __uint_as_float(hi << 16);
    const float r1 = __uint_as_float(hi & 0xffff0000u);
    lo = bf16x2_rn(f0 - r0, f1 - r1);
}
// permuted B-weight byte offset within a row (lane's two fragment regs adjacent)
__device__ __forceinline__ uint32_t bperm_off(int k) {
    const int kt = k >> 4, r = k & 15;
    return (uint32_t)(kt * 32 + ((r & 7) >> 1) * 8 + (r >> 3) * 4 + (r & 1) * 2);
}

// ===========================================================================
// Batched MLP via mma.sync bf16 (split-3, fp32 accum).
// 256 threads = 8 warps, 2 blocks/SM; each warp owns 32 points per iter.
// Layer1 computed DIRECTLY in A-fragment layout; biases folded into C init.
// mode 0: coarse (t from near/far); mode 1: fine (t from g_z).
// ===========================================================================
__global__ void __launch_bounds__(BLK, 2) mlp_kernel(
    int mode, int wtotal,
    const float* __restrict__ origins, const float* __restrict__ dirs,
    const float* __restrict__ nearp, const float* __restrict__ farp,
    const float* __restrict__ W1, const float* __restrict__ B1,
    const float* __restrict__ W2, const float* __restrict__ B2,
    const float* __restrict__ WR, const float* __restrict__ BR,
    const float* __restrict__ WD, const float* __restrict__ BD,
    float4* __restrict__ outp)
{
    __shared__ __align__(16) char sW2H[64 * HROW];   // W2^T [n][perm k] bf16
    __shared__ __align__(16) char sW2L[64 * HROW];
    __shared__ __align__(16) char sW3H[8 * HROW];    // [rgb,d,0..0][perm k]
    __shared__ __align__(16) char sW3L[8 * HROW];
    __shared__ __align__(16) float4 sW14[64];        // {w1x, w1y, w1z, b1}
    __shared__ __align__(16) float sB2[64];
    __shared__ __align__(16) float sBR8[8];          // {br0,br1,br2,bd,0,0,0,0}
    __shared__ __align__(16) float sOut[WPB][32][4];

    const int tid = threadIdx.x;
    const int warp = tid >> 5;
    const int lane = tid & 31;

    // ---- stage weights (permuted k layout) ----
    for (int e = tid; e < 4096; e += BLK) {
        const int n = e >> 6, k = e & 63;
        const float w = W2[k * 64 + n];
        const __nv_bfloat16 hb = __float2bfloat16(w);
        const uint32_t off = (uint32_t)n * HROW + bperm_off(k);
        *(__nv_bfloat16*)(sW2H + off) = hb;
        *(__nv_bfloat16*)(sW2L + off) = __float2bfloat16(w - __bfloat162float(hb));
    }
    for (int e = tid; e < 512; e += BLK) {
        const int n = e >> 6, k = e & 63;
        const float w = (n < 3) ? WR[k * 3 + n] : ((n == 3) ? WD[k] : 0.0f);
        const __nv_bfloat16 hb = __float2bfloat16(w);
        const uint32_t off = (uint32_t)n * HROW + bperm_off(k);
        *(__nv_bfloat16*)(sW3H + off) = hb;
        *(__nv_bfloat16*)(sW3L + off) = __float2bfloat16(w - __bfloat162float(hb));
    }
    for (int e = tid; e < 64; e += BLK) {
        sW14[e] = make_float4(W1[e], W1[64 + e], W1[128 + e], B1[e]);
        sB2[e] = B2[e];
    }
    if (tid < 8) sBR8[tid] = (tid < 3) ? BR[tid] : ((tid == 3) ? BD[0] : 0.0f);
    __syncthreads();

    const uint32_t w2hB = smem_u32(sW2H);
    const uint32_t w2lB = smem_u32(sW2L);
    const uint32_t w3hB = smem_u32(sW3H);
    const uint32_t w3lB = smem_u32(sW3L);
    const uint32_t b2B  = smem_u32(sB2);
    const uint32_t br8B = smem_u32(sBR8);

    const int g = lane >> 2;
    const int j0 = (lane & 3) * 2;
    const uint32_t bOff = (uint32_t)g * HROW + (uint32_t)(lane & 3) * 8;

    for (int wt = blockIdx.x * WPB + warp; wt < wtotal; wt += gridDim.x * WPB) {
        // ---- ray + per-lane t values (tile = 32 points, within one ray) ----
        const int ray = (mode == 0) ? (wt >> 1) : (wt / 6);
        const float ox = origins[3 * ray + 0], oy = origins[3 * ray + 1], oz = origins[3 * ray + 2];
        const float dx = dirs[3 * ray + 0], dy = dirs[3 * ray + 1], dz = dirs[3 * ray + 2];
        float tv[4];
        if (mode == 0) {
            const float nb = nearp[ray], fb = farp[ray];
            const int base = (wt & 1) * 32;
#pragma unroll
            for (int a = 0; a < 4; ++a) {
                const float u = (float)(base + 8 * a + g) * (1.0f / 63.0f);
                tv[a] = nb * (1.0f - u) + fb * u;
            }
        } else {
#pragma unroll
            for (int a = 0; a < 4; ++a)
                tv[a] = g_z[wt * 32 + 8 * a + g];
        }

        // ---- positions hoisted (kt-invariant): 4 points per lane ----
        float pX[4], pY[4], pZ[4];
#pragma unroll
        for (int a = 0; a < 4; ++a) {
            pX[a] = fmaf(tv[a], dx, ox);
            pY[a] = fmaf(tv[a], dy, oy);
            pZ[a] = fmaf(tv[a], dz, oz);
        }

        // ---- C init = b2 bias (folds layer2 bias; replaces zero-init) ----
        float C[MT][8][4];
#pragma unroll
        for (int nt = 0; nt < 8; ++nt) {
            uint32_t bx, by;
            lds64(b2B + (uint32_t)(nt * 8 + j0) * 4, bx, by);
            const float fx = __uint_as_float(bx), fy = __uint_as_float(by);
#pragma unroll
            for (int mt = 0; mt < MT; ++mt) {
                C[mt][nt][0] = fx; C[mt][nt][1] = fy;
                C[mt][nt][2] = fx; C[mt][nt][3] = fy;
            }
        }

        // ---- layer1 fragment-direct + layer2 MMA ----
#pragma unroll
        for (int kt = 0; kt < 4; ++kt) {
            const int c0 = kt * 16 + j0;
            const float4 wa = sW14[c0], wb = sW14[c0 + 1];
            const float4 wc = sW14[c0 + 8], wd = sW14[c0 + 9];

            uint32_t Ah[MT][4], Al[MT][4];
#pragma unroll
            for (int mt = 0; mt < MT; ++mt) {
                const int a0 = 2 * mt, a1 = 2 * mt + 1;
                const float v00 = fmaxf(fmaf(pX[a0], wa.x, fmaf(pY[a0], wa.y, fmaf(pZ[a0], wa.z, wa.w))), 0.0f);
                const float v01 = fmaxf(fmaf(pX[a0], wb.x, fmaf(pY[a0], wb.y, fmaf(pZ[a0], wb.z, wb.w))), 0.0f);
                const float v02 = fmaxf(fmaf(pX[a0], wc.x, fmaf(pY[a0], wc.y, fmaf(pZ[a0], wc.z, wc.w))), 0.0f);
                const float v03 = fmaxf(fmaf(pX[a0], wd.x, fmaf(pY[a0], wd.y, fmaf(pZ[a0], wd.z, wd.w))), 0.0f);
                const float v10 = fmaxf(fmaf(pX[a1], wa.x, fmaf(pY[a1], wa.y, fmaf(pZ[a1], wa.z, wa.w))), 0.0f);
                const float v11 = fmaxf(fmaf(pX[a1], wb.x, fmaf(pY[a1], wb.y, fmaf(pZ[a1], wb.z, wb.w))), 0.0f);
                const float v12 = fmaxf(fmaf(pX[a1], wc.x, fmaf(pY[a1], wc.y, fmaf(pZ[a1], wc.z, wc.w))), 0.0f);
                const float v13 = fmaxf(fmaf(pX[a1], wd.x, fmaf(pY[a1], wd.y, fmaf(pZ[a1], wd.z, wd.w))), 0.0f);
                split2(v00, v01, Ah[mt][0], Al[mt][0]);
                split2(v10, v11, Ah[mt][1], Al[mt][1]);
                split2(v02, v03, Ah[mt][2], Al[mt][2]);
                split2(v12, v13, Ah[mt][3], Al[mt][3]);
            }
#pragma unroll
            for (int hf = 0; hf < 2; ++hf) {
                uint32_t bh[4][2], bl[4][2];
#pragma unroll
                for (int n4 = 0; n4 < 4; ++n4) {
                    const uint32_t ba = (uint32_t)(hf * 4 + n4) * (8 * HROW) + bOff + kt * 32;
                    lds64(w2hB + ba, bh[n4][0], bh[n4][1]);
                    lds64(w2lB + ba, bl[n4][0], bl[n4][1]);
                }
#pragma unroll
                for (int mt = 0; mt < MT; ++mt)
#pragma unroll
                    for (int n4 = 0; n4 < 4; ++n4) {
                        float* Cp = C[mt][hf * 4 + n4];
                        mma16816(Cp, Ah[mt], bh[n4][0], bh[n4][1]);
                        mma16816(Cp, Ah[mt], bl[n4][0], bl[n4][1]);
                        mma16816(Cp, Al[mt], bh[n4][0], bh[n4][1]);
                    }
            }
        }

        // ---- C3 init = output bias (folds br/bd) ----
        float C3[MT][4];
        {
            uint32_t bx, by;
            lds64(br8B + (uint32_t)j0 * 4, bx, by);
            const float fx = __uint_as_float(bx), fy = __uint_as_float(by);
#pragma unroll
            for (int mt = 0; mt < MT; ++mt) {
                C3[mt][0] = fx; C3[mt][1] = fy;
                C3[mt][2] = fx; C3[mt][3] = fy;
            }
        }

        // ---- layer3: A3 repacked straight from C regs (bias already in C) ----
#pragma unroll
        for (int kt = 0; kt < 4; ++kt) {
            const int nt0 = 2 * kt, nt1 = 2 * kt + 1;
            uint32_t b3h0, b3h1, b3l0, b3l1;
            lds64(w3hB + bOff + kt * 32, b3h0, b3h1);
            lds64(w3lB + bOff + kt * 32, b3l0, b3l1);
#pragma unroll
            for (int mt = 0; mt < MT; ++mt) {
                const float v00 = fmaxf(C[mt][nt0][0], 0.0f);
                const float v01 = fmaxf(C[mt][nt0][1], 0.0f);
                const float v02 = fmaxf(C[mt][nt0][2], 0.0f);
                const float v03 = fmaxf(C[mt][nt0][3], 0.0f);
                const float v10 = fmaxf(C[mt][nt1][0], 0.0f);
                const float v11 = fmaxf(C[mt][nt1][1], 0.0f);
                const float v12 = fmaxf(C[mt][nt1][2], 0.0f);
                const float v13 = fmaxf(C[mt][nt1][3], 0.0f);
                uint32_t A3h[4], A3l[4];
                split2(v00, v01, A3h[0], A3l[0]);
                split2(v02, v03, A3h[1], A3l[1]);
                split2(v10, v11, A3h[2], A3l[2]);
                split2(v12, v13, A3h[3], A3l[3]);
                mma16816(C3[mt], A3h, b3h0, b3h1);
                mma16816(C3[mt], A3h, b3l0, b3l1);
                mma16816(C3[mt], A3l, b3h0, b3h1);
            }
        }

        // ---- transpose via sOut, activate, store (bias already included) ----
        if ((lane & 3) < 2) {
#pragma unroll
            for (int mt = 0; mt < MT; ++mt) {
                const int r0 = mt * 16 + g;
                *(float2*)&sOut[warp][r0][j0] = make_float2(C3[mt][0], C3[mt][1]);
                *(float2*)&sOut[warp][r0 + 8][j0] = make_float2(C3[mt][2], C3[mt][3]);
            }
        }
        __syncwarp();
        {
            const float4 o4 = *(const float4*)&sOut[warp][lane][0];
            outp[wt * 32 + lane] = make_float4(1.0f / (1.0f + __expf(-o4.x)),
                                              1.0f / (1.0f + __expf(-o4.y)),
                                              1.0f / (1.0f + __expf(-o4.z)),
                                              fmaxf(o4.w, 0.0f));
        }
        __syncwarp();
    }
}

// ===========================================================================
// Coarse render: warp/ray, 2 samples/lane.
// ===========================================================================
__global__ void __launch_bounds__(256) coarse_render(
    const float* __restrict__ origins, const float* __restrict__ dirs,
    const float* __restrict__ nearp, const float* __restrict__ farp,
    const float* __restrict__ bkgd, float* __restrict__ out)
{
    const int lane = threadIdx.x & 31;
    const int ray = blockIdx.x * 8 + (threadIdx.x >> 5);
    const int i0 = 2 * lane, i1 = 2 * lane + 1;

    const float nb = nearp[ray], fb = farp[ray];
    const float ti0 = (float)i0 * (1.0f / 63.0f);
    const float ti1 = (float)i1 * (1.0f / 63.0f);
    const float ti2 = (float)(i1 + 1) * (1.0f / 63.0f);
    const float t0 = nb * (1.0f - ti0) + fb * ti0;
    const float t1 = nb * (1.0f - ti1) + fb * ti1;
    const float t2 = nb * (1.0f - ti2) + fb * ti2;

    const float dx = dirs[3 * ray + 0], dy = dirs[3 * ray + 1], dz = dirs[3 * ray + 2];
    const float dn = sqrtf(dx * dx + dy * dy + dz * dz);

    const float4 q0 = g_rgbd[ray * NCS + i0];
    const float4 q1 = g_rgbd[ray * NCS + i1];
    const float dd0 = q0.w * (t1 - t0) * dn;
    const float dd1 = q1.w * ((i1 == 63) ? 1e10f : (t2 - t1)) * dn;

    float s = dd0 + dd1;
#pragma unroll
    for (int off = 1; off < 32; off <<= 1) {
        float n = __shfl_up_sync(0xffffffffu, s, off);
        if (lane >= off) s += n;
    }
    const float prev = __shfl_up_sync(0xffffffffu, s, 1);
    const float excl = (lane == 0) ? 0.0f : prev;

    const float w0 = (1.0f - __expf(-dd0)) * __expf(-excl);
    const float w1 = (1.0f - __expf(-dd1)) * __expf(-(excl + dd0));
    {
        unsigned long long pk;
        asm("mov.b64 %0, {%1, %2};" : "=l"(pk) : "f"(w0), "f"(w1));
        reinterpret_cast<unsigned long long*>(g_w)[ray * 32 + lane] = pk;
    }

    const float n0 = nearp[0], f0 = farp[0];
    const float t00 = n0 * (1.0f - ti0) + f0 * ti0;
    const float t01 = n0 * (1.0f - ti1) + f0 * ti1;

    float v[6] = { fmaf(w0, q0.x, w1 * q1.x), fmaf(w0, q0.y, w1 * q1.y),
                   fmaf(w0, q0.z, w1 * q1.z), w0 + w1,
                   fmaf(w0, t0, w1 * t1), fmaf(w0, t00, w1 * t01) };
#pragma unroll
    for (int q = 0; q < 6; ++q) {
#pragma unroll
        for (int off = 16; off >= 1; off >>= 1)
            v[q] += __shfl_xor_sync(0xffffffffu, v[q], off);
    }
    if (lane == 0) {
        const float acc = v[3], om = 1.0f - acc;
        float* o = out + (size_t)ray * 16;
        o[0] = v[0] + bkgd[0] * om;
        o[1] = v[1] + bkgd[1] * om;
        o[2] = v[2] + bkgd[2] * om;
        o[3] = v[4];
        o[4] = acc;
        o[5] = fmaf(v[5], dirs[0], acc * origins[0]);
        o[6] = fmaf(v[5], dirs[1], acc * origins[1]);
        o[7] = fmaf(v[5], dirs[2], acc * origins[2]);
    }
}

// ===========================================================================
// Parallel inverse-CDF + rank-merge: warp per ray.
// ===========================================================================
#define TVAL(idx) (nb * (1.0f - (float)(idx) * (1.0f/63.0f)) + fb * ((float)(idx) * (1.0f/63.0f)))
#define BINV(idx) (0.5f * (TVAL(idx) + TVAL((idx)+1)))

__global__ void __launch_bounds__(256) sample_kernel(
    const float* __restrict__ nearp, const float* __restrict__ farp)
{
    __shared__ float scdf[8][64];
    __shared__ float szs[8][128];
    const int warp = threadIdx.x >> 5;
    const int lane = threadIdx.x & 31;
    const int ray = blockIdx.x * 8 + warp;
    const float nb = nearp[ray], fb = farp[ray];
    const float* gw = g_w + ray * NCS;

    const float wA = gw[1 + lane];
    const float wB = (lane < 30) ? gw[33 + lane] : 0.0f;
    float tsum = wA + wB;
#pragma unroll
    for (int off = 16; off >= 1; off >>= 1)
        tsum += __shfl_xor_sync(0xffffffffu, tsum, off);
    const float pad = fmaxf(1e-5f - tsum, 0.0f);
    const float padd = pad * (1.0f / 62.0f);
    const float inv = 1.0f / (tsum + pad);
    const float pA = (wA + padd) * inv;
    const float pB = (wB + padd) * inv;

    float s1 = pA, s2 = pB;
#pragma unroll
    for (int off = 1; off < 32; off <<= 1) {
        float n1 = __shfl_up_sync(0xffffffffu, s1, off);
        float n2 = __shfl_up_sync(0xffffffffu, s2, off);
        if (lane >= off) { s1 += n1; s2 += n2; }
    }
    const float T1 = __shfl_sync(0xffffffffu, s1, 31);
    if (lane == 0) scdf[warp][0] = 0.0f;
    scdf[warp][1 + lane] = fminf(s1, 1.0f);
    if (lane < 29) scdf[warp][33 + lane] = fminf(T1 + s2, 1.0f);
    if (lane == 31) scdf[warp][62] = 1.0f;
    __syncwarp();

    const float* cdf = scdf[warp];
    const float du = (1.0f - 1.1920929e-7f) * (1.0f / 127.0f);
    float zloc[4];
#pragma unroll
    for (int s = 0; s < 4; ++s) {
        const int sidx = lane * 4 + s;
        const float u = (float)sidx * du;
        int k = 0;
#pragma unroll
        for (int st = 32; st >= 1; st >>= 1)
            if (k + st <= 61 && cdf[k + st] <= u) k += st;
        const float c0 = cdf[k], c1 = cdf[k + 1];
        float tt = (u - c0) / (c1 - c0);
        tt = fminf(fmaxf(tt, 0.0f), 1.0f);
        const float b0 = BINV(k), b1 = BINV(k + 1);
        zloc[s] = b0 + tt * (b1 - b0);
        szs[warp][sidx] = zloc[s];
    }
    __syncwarp();

    float* zout = g_z + (size_t)ray * NTS;
#pragma unroll
    for (int s = 0; s < 4; ++s) {
        const int sidx = lane * 4 + s;
        const float z = zloc[s];
        int i0 = (int)floorf((z - nb) / (fb - nb) * 63.0f);
        i0 = max(-1, min(63, i0));
        while (i0 + 1 <= 63 && TVAL(i0 + 1) <= z) ++i0;
        while (i0 >= 0 && TVAL(i0) > z) --i0;
        zout[sidx + i0 + 1] = z;
    }
#pragma unroll
    for (int r = 0; r < 2; ++r) {
        const int i = lane * 2 + r;
        const float tvv = TVAL(i);
        int c = 0;
#pragma unroll
        for (int st = 128; st >= 1; st >>= 1)
            if (c + st <= 128 && szs[warp][c + st - 1] < tvv) c += st;
        zout[i + c] = tvv;
    }
}
#undef TVAL
#undef BINV

// ===========================================================================
// Fine render: warp/ray, 6 samples/lane.
// ===========================================================================
__global__ void __launch_bounds__(256) fine_render(
    const float* __restrict__ origins, const float* __restrict__ dirs,
    const float* __restrict__ bkgd, float* __restrict__ out)
{
    const int lane = threadIdx.x & 31;
    const int ray = blockIdx.x * 8 + (threadIdx.x >> 5);
    const float4* sc = g_rgbd + RAYS * NCS + (size_t)ray * NTS;
    const float* zr = g_z + (size_t)ray * NTS;
    const int j0 = lane * 6;

    const float dx = dirs[3 * ray + 0], dy = dirs[3 * ray + 1], dz = dirs[3 * ray + 2];
    const float dn = sqrtf(dx * dx + dy * dy + dz * dz);

    float z[7];
#pragma unroll
    for (int s = 0; s < 6; ++s) z[s] = zr[j0 + s];
    z[6] = (lane == 31) ? 0.0f : zr[j0 + 6];

    float dd[6], pre[6];
    float running = 0.0f;
#pragma unroll
    for (int s = 0; s < 6; ++s) {
        const float td = (lane == 31 && s == 5) ? 1e10f : (z[s + 1] - z[s]);
        dd[s] = sc[j0 + s].w * td * dn;
        running += dd[s];
        pre[s] = running;
    }

    float ssum = pre[5];
#pragma unroll
    for (int off = 1; off < 32; off <<= 1) {
        float n = __shfl_up_sync(0xffffffffu, ssum, off);
        if (lane >= off) ssum += n;
    }
    const float prev = __shfl_up_sync(0xffffffffu, ssum, 1);
    const float base = (lane == 0) ? 0.0f : prev;

    float v[6] = {0.0f, 0.0f, 0.0f, 0.0f, 0.0f, 0.0f};
#pragma unroll
    for (int s = 0; s < 6; ++s) {
        const float excl = base + ((s == 0) ? 0.0f : pre[s - 1]);
        const float w = (1.0f - __expf(-dd[s])) * __expf(-excl);
        const float4 q = sc[j0 + s];
        v[0] = fmaf(w, q.x, v[0]);
        v[1] = fmaf(w, q.y, v[1]);
        v[2] = fmaf(w, q.z, v[2]);
        v[3] += w;
        v[4] = fmaf(w, z[s], v[4]);
        v[5] = fmaf(w, g_z[j0 + s], v[5]);   // ray-0 z (pts1 quirk)
    }
#pragma unroll
    for (int q = 0; q < 6; ++q) {
#pragma unroll
        for (int off = 16; off >= 1; off >>= 1)
            v[q] += __shfl_xor_sync(0xffffffffu, v[q], off);
    }
    if (lane == 0) {
        const float acc = v[3], om = 1.0f - acc;
        float* o = out + (size_t)ray * 16;
        o[8]  = v[0] + bkgd[0] * om;
        o[9]  = v[1] + bkgd[1] * om;
        o[10] = v[2] + bkgd[2] * om;
        o[11] = v[4];
        o[12] = acc;
        o[13] = fmaf(v[5], dirs[0], acc * origins[0]);
        o[14] = fmaf(v[5], dirs[1], acc * origins[1]);
        o[15] = fmaf(v[5], dirs[2], acc * origins[2]);
    }
}

// ===========================================================================
extern "C" void kernel_launch(void* const* d_in, const int* in_sizes, int n_in,
                              void* d_out, int out_size)
{
    (void)in_sizes; (void)n_in; (void)out_size;
    const float* origins = (const float*)d_in[0];
    const float* dirs    = (const float*)d_in[1];
    const float* nearp   = (const float*)d_in[2];
    const float* farp    = (const float*)d_in[3];
    const float* bkgd    = (const float*)d_in[4];
    const float* w1c = (const float*)d_in[5];
    const float* b1c = (const float*)d_in[6];
    const float* w2c = (const float*)d_in[7];
    const float* b2c = (const float*)d_in[8];
    const float* wrc = (const float*)d_in[9];
    const float* brc = (const float*)d_in[10];
    const float* wdc = (const float*)d_in[11];
    const float* bdc = (const float*)d_in[12];
    const float* w1f = (const float*)d_in[13];
    const float* b1f = (const float*)d_in[14];
    const float* w2f = (const float*)d_in[15];
    const float* b2f = (const float*)d_in[16];
    const float* wrf = (const float*)d_in[17];
    const float* brf = (const float*)d_in[18];
    const float* wdf = (const float*)d_in[19];
    const float* bdf = (const float*)d_in[20];
    float* out = (float*)d_out;

    float4* scratch;
    cudaGetSymbolAddress((void**)&scratch, g_rgbd);

    const int wt_coarse = RAYS * 2;           // 32 pts/tile, 2 tiles per coarse ray
    const int wt_fine   = RAYS * 6;           // 6 tiles per fine ray

    mlp_kernel<<<296, BLK>>>(0, wt_coarse, origins, dirs, nearp, farp,
                             w1c, b1c, w2c, b2c, wrc, brc, wdc, bdc, scratch);
    coarse_render<<<RAYS / 8, 256>>>(origins, dirs, nearp, farp, bkgd, out);
    sample_kernel<<<RAYS / 8, 256>>>(nearp, farp);
    mlp_kernel<<<296, BLK>>>(1, wt_fine, origins, dirs, nearp, farp,
                             w1f, b1f, w2f, b2f, wrf, brf, wdf, bdf,
                             scratch + RAYS * NCS);
    fine_render<<<RAYS / 8, 256>>>(origins, dirs, bkgd, out);
}